// round 5
// baseline (speedup 1.0000x reference)
#include <cuda_runtime.h>
#include <cuda_bf16.h>
#include <cstdint>

// ---------------------------------------------------------------------------
// MoE layer: B=4,S=2048,D=1024,E=8,F=4096, top-k=2
// Round 5: 4-stage cp.async pipeline (3-tile lead, loads issued right after
// the stage barrier), mma.sync tf32, 512-thread CTAs.
// ---------------------------------------------------------------------------

#define T_TOK   8192
#define DDIM    1024
#define EEXP    8
#define FDIM    4096
#define NASSIGN (T_TOK * 2)
#define SEGPAD  128
#define MAXSLOTS (NASSIGN + EEXP * SEGPAD)  // 17408

__device__ float g_xp[MAXSLOTS * (size_t)DDIM];
__device__ float g_h [MAXSLOTS * (size_t)FDIM];
__device__ float g_y [MAXSLOTS * (size_t)DDIM];
__device__ int   g_te[NASSIGN];
__device__ float g_tw[NASSIGN];
__device__ int   g_slot[NASSIGN];
__device__ int   g_count[EEXP];
__device__ int   g_cursor[EEXP];
__device__ int   g_offs[EEXP + 1];

__device__ __forceinline__ float to_tf32(float v) {
    uint32_t u;
    asm("cvt.rna.tf32.f32 %0, %1;" : "=r"(u) : "f"(v));
    return __uint_as_float(u);
}
__device__ __forceinline__ uint32_t cvt_tf32_u(uint32_t v) {
    uint32_t u;
    asm("cvt.rna.tf32.f32 %0, %1;" : "=r"(u) : "r"(v));
    return u;
}
__device__ __forceinline__ uint32_t smem_u32(const void* p) {
    uint32_t a;
    asm("{ .reg .u64 t; cvta.to.shared.u64 t, %1; cvt.u32.u64 %0, t; }" : "=r"(a) : "l"(p));
    return a;
}
#define CP_ASYNC16(dst, src) \
    asm volatile("cp.async.cg.shared.global [%0], [%1], 16;" :: "r"(dst), "l"(src) : "memory")
#define CP_COMMIT() asm volatile("cp.async.commit_group;" ::: "memory")
#define CP_WAIT(n)  asm volatile("cp.async.wait_group %0;" :: "n"(n) : "memory")

__device__ __forceinline__ void mma_tf32(float* d, const uint32_t* a, const uint32_t* b) {
    asm volatile(
        "mma.sync.aligned.m16n8k8.row.col.f32.tf32.tf32.f32 "
        "{%0,%1,%2,%3}, {%4,%5,%6,%7}, {%8,%9}, {%0,%1,%2,%3};"
        : "+f"(d[0]), "+f"(d[1]), "+f"(d[2]), "+f"(d[3])
        : "r"(a[0]), "r"(a[1]), "r"(a[2]), "r"(a[3]), "r"(b[0]), "r"(b[1]));
}

// ---------------------------------------------------------------------------
__global__ void k_init() {
    int i = threadIdx.x;
    if (i < EEXP) { g_count[i] = 0; g_cursor[i] = 0; }
}

// Gate: one warp per token.
__global__ void k_gate(const float* __restrict__ x, const float* __restrict__ Wg) {
    int t = blockIdx.x * 8 + (threadIdx.x >> 5);
    int lane = threadIdx.x & 31;
    const float* xr = x + (size_t)t * DDIM;

    float acc[EEXP];
#pragma unroll
    for (int e = 0; e < EEXP; e++) acc[e] = 0.f;
#pragma unroll 4
    for (int i = 0; i < DDIM / 32; i++) {
        int d = i * 32 + lane;
        float xv = xr[d];
        const float4* wr = (const float4*)(Wg + (size_t)d * EEXP);
        float4 w0 = wr[0], w1 = wr[1];
        acc[0] += xv * w0.x; acc[1] += xv * w0.y;
        acc[2] += xv * w0.z; acc[3] += xv * w0.w;
        acc[4] += xv * w1.x; acc[5] += xv * w1.y;
        acc[6] += xv * w1.z; acc[7] += xv * w1.w;
    }
#pragma unroll
    for (int off = 16; off > 0; off >>= 1)
#pragma unroll
        for (int e = 0; e < EEXP; e++)
            acc[e] += __shfl_xor_sync(0xffffffffu, acc[e], off);

    if (lane == 0) {
        int i1 = 0;
#pragma unroll
        for (int e = 1; e < EEXP; e++) if (acc[e] > acc[i1]) i1 = e;
        int i2 = -1;
#pragma unroll
        for (int e = 0; e < EEXP; e++) {
            if (e == i1) continue;
            if (i2 < 0 || acc[e] > acc[i2]) i2 = e;
        }
        float wa = 1.f / (1.f + expf(acc[i2] - acc[i1]));
        g_te[2 * t] = i1;  g_te[2 * t + 1] = i2;
        g_tw[2 * t] = wa;  g_tw[2 * t + 1] = 1.f - wa;
        atomicAdd(&g_count[i1], 1);
        atomicAdd(&g_count[i2], 1);
    }
}

__global__ void k_offs() {
    if (threadIdx.x == 0) {
        int o = 0;
#pragma unroll
        for (int e = 0; e < EEXP; e++) {
            g_offs[e] = o;
            o += (g_count[e] + SEGPAD - 1) & ~(SEGPAD - 1);
            g_cursor[e] = 0;
        }
        g_offs[EEXP] = o;
    }
}

// Gather + round to tf32 (RNA) so the MMA truncation is lossless.
__global__ void k_gather(const float* __restrict__ x) {
    int a = blockIdx.x * 8 + (threadIdx.x >> 5);
    int lane = threadIdx.x & 31;
    if (a >= NASSIGN) return;
    int t = a >> 1;
    int e = g_te[a];
    int slot = 0;
    if (lane == 0) {
        slot = g_offs[e] + atomicAdd(&g_cursor[e], 1);
        g_slot[a] = slot;
    }
    slot = __shfl_sync(0xffffffffu, slot, 0);
    const float4* src = (const float4*)(x + (size_t)t * DDIM);
    float4* dst = (float4*)(g_xp + (size_t)slot * DDIM);
#pragma unroll
    for (int i = 0; i < 8; i++) {
        float4 v = src[lane + 32 * i];
        v.x = to_tf32(v.x); v.y = to_tf32(v.y);
        v.z = to_tf32(v.z); v.w = to_tf32(v.w);
        dst[lane + 32 * i] = v;
    }
}

__global__ void k_zeropad() {
    int e = blockIdx.x;
    int start = g_offs[e] + g_count[e];
    int end = g_offs[e + 1];
    for (int r = start + (int)blockIdx.y; r < end; r += (int)gridDim.y) {
        float4* dst = (float4*)(g_xp + (size_t)r * DDIM);
        for (int i = threadIdx.x; i < DDIM / 4; i += 256)
            dst[i] = make_float4(0.f, 0.f, 0.f, 0.f);
    }
}

__device__ __forceinline__ float gelu_tanh(float v) {
    float v3 = v * v * v;
    return 0.5f * v * (1.f + tanhf(0.7978845608028654f * (v + 0.044715f * v3)));
}

// ---------------------------------------------------------------------------
// mma.sync tf32 GEMM: C[m][n] = A[m][k] * W[e][k][n] over padded segments.
// BM=128, BN=256, BK=32, 512 threads (16 warps, warp tile 64x32), 4 stages.
#define BM 128
#define BN 256
#define BKF 32
#define NSTAGE 4
#define ASTRIDE 36
#define BSTRIDE 264
#define AS_ELEMS (BM * ASTRIDE)    // 4608
#define BS_ELEMS (BKF * BSTRIDE)   // 8448
#define SMEM_GEMM (NSTAGE * (AS_ELEMS + BS_ELEMS) * 4)  // 208896

__global__ __launch_bounds__(512, 1)
void k_gemm_mma(const float* __restrict__ W, int K, int Ntot, int doGelu) {
    int row0 = blockIdx.x * BM;
    if (row0 >= g_offs[EEXP]) return;
    int e = 0;
    while (g_offs[e + 1] <= row0) e++;

    extern __shared__ float smem[];
    float* As = smem;                      // [NSTAGE][BM][ASTRIDE]
    float* Bs = smem + NSTAGE * AS_ELEMS;  // [NSTAGE][BKF][BSTRIDE]

    int tid = threadIdx.x, wid = tid >> 5, lane = tid & 31;
    int gid = lane >> 2, tig = lane & 3;
    int warp_m = wid & 1, warp_n = wid >> 1;   // 2 x 8 warps, tile 64x32

    const float* A = doGelu ? g_xp : g_h;
    float* C       = doGelu ? g_h  : g_y;
    const float* B = W + (size_t)e * K * Ntot + (size_t)blockIdx.y * BN;

    int ar = tid >> 3, ac = (tid & 7) * 4;
    int br = tid >> 6, bc = (tid & 63) * 4;

    const float* asrc0 = A + (size_t)(row0 + ar) * K + ac;
    const float* asrc1 = A + (size_t)(row0 + ar + 64) * K + ac;
    const float* bsrc0 = B + (size_t)br * Ntot + bc;

    uint32_t sbase = smem_u32(smem);
    uint32_t a_d0 = sbase + ((uint32_t)ar * ASTRIDE + ac) * 4;
    uint32_t a_d1 = a_d0 + 64u * ASTRIDE * 4;
    uint32_t b_d0 = sbase + (uint32_t)NSTAGE * AS_ELEMS * 4 + ((uint32_t)br * BSTRIDE + bc) * 4;

    float acc[4][4][4];
#pragma unroll
    for (int mt = 0; mt < 4; mt++)
#pragma unroll
        for (int nt = 0; nt < 4; nt++)
#pragma unroll
            for (int j = 0; j < 4; j++) acc[mt][nt][j] = 0.f;

    int KT = K / BKF;   // 32 or 128 (always >= 4)

#define LOAD_TILE(kt, st) do { \
    int _k0 = (kt) * BKF; \
    uint32_t _ao = (uint32_t)(st) * AS_ELEMS * 4; \
    uint32_t _bo = (uint32_t)(st) * BS_ELEMS * 4; \
    CP_ASYNC16(a_d0 + _ao, asrc0 + _k0); \
    CP_ASYNC16(a_d1 + _ao, asrc1 + _k0); \
    CP_ASYNC16(b_d0 + _bo,                      bsrc0 + (size_t)_k0 * Ntot); \
    CP_ASYNC16(b_d0 + _bo +  8u * BSTRIDE * 4,  bsrc0 + (size_t)(_k0 + 8)  * Ntot); \
    CP_ASYNC16(b_d0 + _bo + 16u * BSTRIDE * 4,  bsrc0 + (size_t)(_k0 + 16) * Ntot); \
    CP_ASYNC16(b_d0 + _bo + 24u * BSTRIDE * 4,  bsrc0 + (size_t)(_k0 + 24) * Ntot); \
} while (0)

    // prologue: tiles 0,1,2 into stages 0,1,2 (one group each)
    LOAD_TILE(0, 0); CP_COMMIT();
    LOAD_TILE(1, 1); CP_COMMIT();
    LOAD_TILE(2, 2); CP_COMMIT();

    int stage = 0;
    for (int kt = 0; kt < KT; kt++) {
        CP_WAIT(2);          // tile kt resident (2 younger groups may be in flight)
        __syncthreads();     // stage (kt-1)%4 now free for reuse
        int nkt = kt + 3;
        if (nkt < KT) {
            int nst = stage + 3; if (nst >= NSTAGE) nst -= NSTAGE;
            LOAD_TILE(nkt, nst);
        }
        CP_COMMIT();         // commit every iter: group count stays uniform

        const float* at = As + stage * AS_ELEMS + (warp_m * 64 + gid) * ASTRIDE;
        const float* bt = Bs + stage * BS_ELEMS + tig * BSTRIDE + warp_n * 32 + gid;
#pragma unroll
        for (int ks = 0; ks < 4; ks++) {
            int k0 = ks * 8;
            uint32_t afrag[4][4];
#pragma unroll
            for (int mt = 0; mt < 4; mt++) {
                const float* ap = at + mt * 16 * ASTRIDE + k0 + tig;
                afrag[mt][0] = __float_as_uint(ap[0]);
                afrag[mt][1] = __float_as_uint(ap[8 * ASTRIDE]);
                afrag[mt][2] = __float_as_uint(ap[4]);
                afrag[mt][3] = __float_as_uint(ap[8 * ASTRIDE + 4]);
            }
            uint32_t bfrag[4][2];
#pragma unroll
            for (int nt = 0; nt < 4; nt++) {
                const float* bp = bt + (size_t)k0 * BSTRIDE + nt * 8;
                bfrag[nt][0] = cvt_tf32_u(__float_as_uint(bp[0]));
                bfrag[nt][1] = cvt_tf32_u(__float_as_uint(bp[4 * BSTRIDE]));
            }
#pragma unroll
            for (int mt = 0; mt < 4; mt++)
#pragma unroll
                for (int nt = 0; nt < 4; nt++)
                    mma_tf32(acc[mt][nt], afrag[mt], bfrag[nt]);
        }
        stage++; if (stage >= NSTAGE) stage = 0;
    }

    // epilogue
#pragma unroll
    for (int mt = 0; mt < 4; mt++) {
        int mrow = row0 + warp_m * 64 + mt * 16 + gid;
#pragma unroll
        for (int nt = 0; nt < 4; nt++) {
            int col = blockIdx.y * BN + warp_n * 32 + nt * 8 + 2 * tig;
            float2 v0 = make_float2(acc[mt][nt][0], acc[mt][nt][1]);
            float2 v1 = make_float2(acc[mt][nt][2], acc[mt][nt][3]);
            if (doGelu) {
                v0.x = to_tf32(gelu_tanh(v0.x)); v0.y = to_tf32(gelu_tanh(v0.y));
                v1.x = to_tf32(gelu_tanh(v1.x)); v1.y = to_tf32(gelu_tanh(v1.y));
            }
            *(float2*)(C + (size_t)mrow * Ntot + col) = v0;
            *(float2*)(C + (size_t)(mrow + 8) * Ntot + col) = v1;
        }
    }
}

__global__ void k_combine(float* __restrict__ out) {
    int t = blockIdx.x * 8 + (threadIdx.x >> 5);
    int lane = threadIdx.x & 31;
    if (t >= T_TOK) return;
    int a0 = g_slot[2 * t], a1 = g_slot[2 * t + 1];
    float w0 = g_tw[2 * t], w1 = g_tw[2 * t + 1];
    const float4* y0 = (const float4*)(g_y + (size_t)a0 * DDIM);
    const float4* y1 = (const float4*)(g_y + (size_t)a1 * DDIM);
    float4* o = (float4*)(out + (size_t)t * DDIM);
#pragma unroll
    for (int i = 0; i < 8; i++) {
        int idx = lane + 32 * i;
        float4 p = y0[idx], q = y1[idx];
        o[idx] = make_float4(w0 * p.x + w1 * q.x, w0 * p.y + w1 * q.y,
                             w0 * p.z + w1 * q.z, w0 * p.w + w1 * q.w);
    }
}

// ---------------------------------------------------------------------------
extern "C" void kernel_launch(void* const* d_in, const int* in_sizes, int n_in,
                              void* d_out, int out_size) {
    const float* x  = (const float*)d_in[0];
    const float* Wg = (const float*)d_in[1];
    const float* w1 = (const float*)d_in[2];
    const float* w2 = (const float*)d_in[3];
    float* out = (float*)d_out;

    cudaFuncSetAttribute(k_gemm_mma, cudaFuncAttributeMaxDynamicSharedMemorySize, SMEM_GEMM);

    k_init<<<1, 32>>>();
    k_gate<<<T_TOK / 8, 256>>>(x, Wg);
    k_offs<<<1, 32>>>();
    k_gather<<<NASSIGN / 8, 256>>>(x);
    k_zeropad<<<dim3(EEXP, 8), 256>>>();

    dim3 grid1(MAXSLOTS / BM, FDIM / BN);   // (136, 16)
    k_gemm_mma<<<grid1, 512, SMEM_GEMM>>>(w1, DDIM, FDIM, 1);

    dim3 grid2(MAXSLOTS / BM, DDIM / BN);   // (136, 4)
    k_gemm_mma<<<grid2, 512, SMEM_GEMM>>>(w2, FDIM, DDIM, 0);

    k_combine<<<T_TOK / 8, 256>>>(out);
}

// round 6
// speedup vs baseline: 1.5605x; 1.5605x over previous
#include <cuda_runtime.h>
#include <cuda_bf16.h>
#include <cstdint>

// ---------------------------------------------------------------------------
// MoE layer: B=4,S=2048,D=1024,E=8,F=4096, top-k=2
// Round 6: round-4 pipeline (3-stage, proven 1836us) + ldmatrix.x4 for A
// fragments (64 LDS.32 -> 16 LDSM per warp per ktile).
// ---------------------------------------------------------------------------

#define T_TOK   8192
#define DDIM    1024
#define EEXP    8
#define FDIM    4096
#define NASSIGN (T_TOK * 2)
#define SEGPAD  128
#define MAXSLOTS (NASSIGN + EEXP * SEGPAD)  // 17408

__device__ float g_xp[MAXSLOTS * (size_t)DDIM];
__device__ float g_h [MAXSLOTS * (size_t)FDIM];
__device__ float g_y [MAXSLOTS * (size_t)DDIM];
__device__ int   g_te[NASSIGN];
__device__ float g_tw[NASSIGN];
__device__ int   g_slot[NASSIGN];
__device__ int   g_count[EEXP];
__device__ int   g_cursor[EEXP];
__device__ int   g_offs[EEXP + 1];

__device__ __forceinline__ float to_tf32(float v) {
    uint32_t u;
    asm("cvt.rna.tf32.f32 %0, %1;" : "=r"(u) : "f"(v));
    return __uint_as_float(u);
}
__device__ __forceinline__ uint32_t cvt_tf32_u(uint32_t v) {
    uint32_t u;
    asm("cvt.rna.tf32.f32 %0, %1;" : "=r"(u) : "r"(v));
    return u;
}
__device__ __forceinline__ uint32_t smem_u32(const void* p) {
    uint32_t a;
    asm("{ .reg .u64 t; cvta.to.shared.u64 t, %1; cvt.u32.u64 %0, t; }" : "=r"(a) : "l"(p));
    return a;
}
#define CP_ASYNC16(dst, src) \
    asm volatile("cp.async.cg.shared.global [%0], [%1], 16;" :: "r"(dst), "l"(src) : "memory")
#define CP_COMMIT() asm volatile("cp.async.commit_group;" ::: "memory")
#define CP_WAIT(n)  asm volatile("cp.async.wait_group %0;" :: "n"(n) : "memory")

__device__ __forceinline__ void mma_tf32(float* d, const uint32_t* a, const uint32_t* b) {
    asm volatile(
        "mma.sync.aligned.m16n8k8.row.col.f32.tf32.tf32.f32 "
        "{%0,%1,%2,%3}, {%4,%5,%6,%7}, {%8,%9}, {%0,%1,%2,%3};"
        : "+f"(d[0]), "+f"(d[1]), "+f"(d[2]), "+f"(d[3])
        : "r"(a[0]), "r"(a[1]), "r"(a[2]), "r"(a[3]), "r"(b[0]), "r"(b[1]));
}
__device__ __forceinline__ void ldsm_x4(uint32_t* r, uint32_t addr) {
    asm volatile("ldmatrix.sync.aligned.m8n8.x4.shared.b16 {%0,%1,%2,%3}, [%4];"
        : "=r"(r[0]), "=r"(r[1]), "=r"(r[2]), "=r"(r[3]) : "r"(addr));
}

// ---------------------------------------------------------------------------
__global__ void k_init() {
    int i = threadIdx.x;
    if (i < EEXP) { g_count[i] = 0; g_cursor[i] = 0; }
}

// Gate: one warp per token.
__global__ void k_gate(const float* __restrict__ x, const float* __restrict__ Wg) {
    int t = blockIdx.x * 8 + (threadIdx.x >> 5);
    int lane = threadIdx.x & 31;
    const float* xr = x + (size_t)t * DDIM;

    float acc[EEXP];
#pragma unroll
    for (int e = 0; e < EEXP; e++) acc[e] = 0.f;
#pragma unroll 4
    for (int i = 0; i < DDIM / 32; i++) {
        int d = i * 32 + lane;
        float xv = xr[d];
        const float4* wr = (const float4*)(Wg + (size_t)d * EEXP);
        float4 w0 = wr[0], w1 = wr[1];
        acc[0] += xv * w0.x; acc[1] += xv * w0.y;
        acc[2] += xv * w0.z; acc[3] += xv * w0.w;
        acc[4] += xv * w1.x; acc[5] += xv * w1.y;
        acc[6] += xv * w1.z; acc[7] += xv * w1.w;
    }
#pragma unroll
    for (int off = 16; off > 0; off >>= 1)
#pragma unroll
        for (int e = 0; e < EEXP; e++)
            acc[e] += __shfl_xor_sync(0xffffffffu, acc[e], off);

    if (lane == 0) {
        int i1 = 0;
#pragma unroll
        for (int e = 1; e < EEXP; e++) if (acc[e] > acc[i1]) i1 = e;
        int i2 = -1;
#pragma unroll
        for (int e = 0; e < EEXP; e++) {
            if (e == i1) continue;
            if (i2 < 0 || acc[e] > acc[i2]) i2 = e;
        }
        float wa = 1.f / (1.f + expf(acc[i2] - acc[i1]));
        g_te[2 * t] = i1;  g_te[2 * t + 1] = i2;
        g_tw[2 * t] = wa;  g_tw[2 * t + 1] = 1.f - wa;
        atomicAdd(&g_count[i1], 1);
        atomicAdd(&g_count[i2], 1);
    }
}

__global__ void k_offs() {
    if (threadIdx.x == 0) {
        int o = 0;
#pragma unroll
        for (int e = 0; e < EEXP; e++) {
            g_offs[e] = o;
            o += (g_count[e] + SEGPAD - 1) & ~(SEGPAD - 1);
            g_cursor[e] = 0;
        }
        g_offs[EEXP] = o;
    }
}

// Gather + round to tf32 (RNA) so the MMA truncation is lossless.
__global__ void k_gather(const float* __restrict__ x) {
    int a = blockIdx.x * 8 + (threadIdx.x >> 5);
    int lane = threadIdx.x & 31;
    if (a >= NASSIGN) return;
    int t = a >> 1;
    int e = g_te[a];
    int slot = 0;
    if (lane == 0) {
        slot = g_offs[e] + atomicAdd(&g_cursor[e], 1);
        g_slot[a] = slot;
    }
    slot = __shfl_sync(0xffffffffu, slot, 0);
    const float4* src = (const float4*)(x + (size_t)t * DDIM);
    float4* dst = (float4*)(g_xp + (size_t)slot * DDIM);
#pragma unroll
    for (int i = 0; i < 8; i++) {
        float4 v = src[lane + 32 * i];
        v.x = to_tf32(v.x); v.y = to_tf32(v.y);
        v.z = to_tf32(v.z); v.w = to_tf32(v.w);
        dst[lane + 32 * i] = v;
    }
}

__global__ void k_zeropad() {
    int e = blockIdx.x;
    int start = g_offs[e] + g_count[e];
    int end = g_offs[e + 1];
    for (int r = start + (int)blockIdx.y; r < end; r += (int)gridDim.y) {
        float4* dst = (float4*)(g_xp + (size_t)r * DDIM);
        for (int i = threadIdx.x; i < DDIM / 4; i += 256)
            dst[i] = make_float4(0.f, 0.f, 0.f, 0.f);
    }
}

__device__ __forceinline__ float gelu_tanh(float v) {
    float v3 = v * v * v;
    return 0.5f * v * (1.f + tanhf(0.7978845608028654f * (v + 0.044715f * v3)));
}

// ---------------------------------------------------------------------------
// mma.sync tf32 GEMM: C[m][n] = A[m][k] * W[e][k][n] over padded segments.
// BM=128, BN=256, BK=32, 512 threads (16 warps, warp tile 64x32), 3 stages.
#define BM 128
#define BN 256
#define BKF 32
#define NSTAGE 3
#define ASTRIDE 36
#define BSTRIDE 264
#define AS_ELEMS (BM * ASTRIDE)    // 4608
#define BS_ELEMS (BKF * BSTRIDE)   // 8448
#define SMEM_GEMM (NSTAGE * (AS_ELEMS + BS_ELEMS) * 4)  // 156672

__global__ __launch_bounds__(512, 1)
void k_gemm_mma(const float* __restrict__ W, int K, int Ntot, int doGelu) {
    int row0 = blockIdx.x * BM;
    if (row0 >= g_offs[EEXP]) return;
    int e = 0;
    while (g_offs[e + 1] <= row0) e++;

    extern __shared__ float smem[];
    float* Bs = smem + NSTAGE * AS_ELEMS;  // [NSTAGE][BKF][BSTRIDE]

    int tid = threadIdx.x, wid = tid >> 5, lane = tid & 31;
    int gid = lane >> 2, tig = lane & 3;
    int warp_m = wid & 1, warp_n = wid >> 1;   // 2 x 8 warps, tile 64x32

    const float* A = doGelu ? g_xp : g_h;
    float* C       = doGelu ? g_h  : g_y;
    const float* B = W + (size_t)e * K * Ntot + (size_t)blockIdx.y * BN;

    int ar = tid >> 3, ac = (tid & 7) * 4;
    int br = tid >> 6, bc = (tid & 63) * 4;

    const float* asrc0 = A + (size_t)(row0 + ar) * K + ac;
    const float* asrc1 = A + (size_t)(row0 + ar + 64) * K + ac;
    const float* bsrc0 = B + (size_t)br * Ntot + bc;

    uint32_t sbase = smem_u32(smem);
    uint32_t a_d0 = sbase + ((uint32_t)ar * ASTRIDE + ac) * 4;
    uint32_t a_d1 = a_d0 + 64u * ASTRIDE * 4;
    uint32_t b_d0 = sbase + (uint32_t)NSTAGE * AS_ELEMS * 4 + ((uint32_t)br * BSTRIDE + bc) * 4;

    // ldmatrix per-lane base: row = lane&15 within 16-row tile, col = (lane>>4)*4.
    uint32_t lm_base = sbase +
        (((uint32_t)(warp_m * 64 + (lane & 15))) * ASTRIDE + ((lane >> 4) << 2)) * 4;

    float acc[4][4][4];
#pragma unroll
    for (int mt = 0; mt < 4; mt++)
#pragma unroll
        for (int nt = 0; nt < 4; nt++)
#pragma unroll
            for (int j = 0; j < 4; j++) acc[mt][nt][j] = 0.f;

    int KT = K / BKF;

#define LOAD_TILE(kt, st) do { \
    int _k0 = (kt) * BKF; \
    uint32_t _ao = (uint32_t)(st) * AS_ELEMS * 4; \
    uint32_t _bo = (uint32_t)(st) * BS_ELEMS * 4; \
    CP_ASYNC16(a_d0 + _ao, asrc0 + _k0); \
    CP_ASYNC16(a_d1 + _ao, asrc1 + _k0); \
    CP_ASYNC16(b_d0 + _bo,                      bsrc0 + (size_t)_k0 * Ntot); \
    CP_ASYNC16(b_d0 + _bo +  8u * BSTRIDE * 4,  bsrc0 + (size_t)(_k0 + 8)  * Ntot); \
    CP_ASYNC16(b_d0 + _bo + 16u * BSTRIDE * 4,  bsrc0 + (size_t)(_k0 + 16) * Ntot); \
    CP_ASYNC16(b_d0 + _bo + 24u * BSTRIDE * 4,  bsrc0 + (size_t)(_k0 + 24) * Ntot); \
} while (0)

    // prologue: tiles 0,1
    LOAD_TILE(0, 0); CP_COMMIT();
    if (KT > 1) LOAD_TILE(1, 1);
    CP_COMMIT();

    int stage = 0;
    for (int kt = 0; kt < KT; kt++) {
        CP_WAIT(1);
        __syncthreads();
        int nkt = kt + 2;
        if (nkt < KT) {
            int nst = stage + 2; if (nst >= NSTAGE) nst -= NSTAGE;
            LOAD_TILE(nkt, nst);
        }
        CP_COMMIT();

        uint32_t a_lm = lm_base + (uint32_t)stage * AS_ELEMS * 4;
        const float* bt = Bs + stage * BS_ELEMS + tig * BSTRIDE + warp_n * 32 + gid;
#pragma unroll
        for (int ks = 0; ks < 4; ks++) {
            int k0 = ks * 8;
            uint32_t afrag[4][4];
#pragma unroll
            for (int mt = 0; mt < 4; mt++)
                ldsm_x4(afrag[mt], a_lm + ((uint32_t)mt * 16 * ASTRIDE + k0) * 4);
            uint32_t bfrag[4][2];
#pragma unroll
            for (int nt = 0; nt < 4; nt++) {
                const float* bp = bt + (size_t)k0 * BSTRIDE + nt * 8;
                bfrag[nt][0] = cvt_tf32_u(__float_as_uint(bp[0]));
                bfrag[nt][1] = cvt_tf32_u(__float_as_uint(bp[4 * BSTRIDE]));
            }
#pragma unroll
            for (int mt = 0; mt < 4; mt++)
#pragma unroll
                for (int nt = 0; nt < 4; nt++)
                    mma_tf32(acc[mt][nt], afrag[mt], bfrag[nt]);
        }
        stage++; if (stage >= NSTAGE) stage = 0;
    }

    // epilogue
#pragma unroll
    for (int mt = 0; mt < 4; mt++) {
        int mrow = row0 + warp_m * 64 + mt * 16 + gid;
#pragma unroll
        for (int nt = 0; nt < 4; nt++) {
            int col = blockIdx.y * BN + warp_n * 32 + nt * 8 + 2 * tig;
            float2 v0 = make_float2(acc[mt][nt][0], acc[mt][nt][1]);
            float2 v1 = make_float2(acc[mt][nt][2], acc[mt][nt][3]);
            if (doGelu) {
                v0.x = to_tf32(gelu_tanh(v0.x)); v0.y = to_tf32(gelu_tanh(v0.y));
                v1.x = to_tf32(gelu_tanh(v1.x)); v1.y = to_tf32(gelu_tanh(v1.y));
            }
            *(float2*)(C + (size_t)mrow * Ntot + col) = v0;
            *(float2*)(C + (size_t)(mrow + 8) * Ntot + col) = v1;
        }
    }
}

__global__ void k_combine(float* __restrict__ out) {
    int t = blockIdx.x * 8 + (threadIdx.x >> 5);
    int lane = threadIdx.x & 31;
    if (t >= T_TOK) return;
    int a0 = g_slot[2 * t], a1 = g_slot[2 * t + 1];
    float w0 = g_tw[2 * t], w1 = g_tw[2 * t + 1];
    const float4* y0 = (const float4*)(g_y + (size_t)a0 * DDIM);
    const float4* y1 = (const float4*)(g_y + (size_t)a1 * DDIM);
    float4* o = (float4*)(out + (size_t)t * DDIM);
#pragma unroll
    for (int i = 0; i < 8; i++) {
        int idx = lane + 32 * i;
        float4 p = y0[idx], q = y1[idx];
        o[idx] = make_float4(w0 * p.x + w1 * q.x, w0 * p.y + w1 * q.y,
                             w0 * p.z + w1 * q.z, w0 * p.w + w1 * q.w);
    }
}

// ---------------------------------------------------------------------------
extern "C" void kernel_launch(void* const* d_in, const int* in_sizes, int n_in,
                              void* d_out, int out_size) {
    const float* x  = (const float*)d_in[0];
    const float* Wg = (const float*)d_in[1];
    const float* w1 = (const float*)d_in[2];
    const float* w2 = (const float*)d_in[3];
    float* out = (float*)d_out;

    cudaFuncSetAttribute(k_gemm_mma, cudaFuncAttributeMaxDynamicSharedMemorySize, SMEM_GEMM);

    k_init<<<1, 32>>>();
    k_gate<<<T_TOK / 8, 256>>>(x, Wg);
    k_offs<<<1, 32>>>();
    k_gather<<<NASSIGN / 8, 256>>>(x);
    k_zeropad<<<dim3(EEXP, 8), 256>>>();

    dim3 grid1(MAXSLOTS / BM, FDIM / BN);   // (136, 16)
    k_gemm_mma<<<grid1, 512, SMEM_GEMM>>>(w1, DDIM, FDIM, 1);

    dim3 grid2(MAXSLOTS / BM, DDIM / BN);   // (136, 4)
    k_gemm_mma<<<grid2, 512, SMEM_GEMM>>>(w2, FDIM, DDIM, 0);

    k_combine<<<T_TOK / 8, 256>>>(out);
}

// round 8
// speedup vs baseline: 1.5678x; 1.0046x over previous
#include <cuda_runtime.h>
#include <cuda_bf16.h>
#include <cstdint>

// ---------------------------------------------------------------------------
// MoE layer: B=4,S=2048,D=1024,E=8,F=4096, top-k=2
// Round 7: BK=64 (halves per-ktile fixed overhead), 2-stage single-barrier
// cp.async pipeline, ldmatrix A fragments, mma.sync tf32.
// ---------------------------------------------------------------------------

#define T_TOK   8192
#define DDIM    1024
#define EEXP    8
#define FDIM    4096
#define NASSIGN (T_TOK * 2)
#define SEGPAD  128
#define MAXSLOTS (NASSIGN + EEXP * SEGPAD)  // 17408

__device__ float g_xp[MAXSLOTS * (size_t)DDIM];
__device__ float g_h [MAXSLOTS * (size_t)FDIM];
__device__ float g_y [MAXSLOTS * (size_t)DDIM];
__device__ int   g_te[NASSIGN];
__device__ float g_tw[NASSIGN];
__device__ int   g_slot[NASSIGN];
__device__ int   g_count[EEXP];
__device__ int   g_cursor[EEXP];
__device__ int   g_offs[EEXP + 1];

__device__ __forceinline__ float to_tf32(float v) {
    uint32_t u;
    asm("cvt.rna.tf32.f32 %0, %1;" : "=r"(u) : "f"(v));
    return __uint_as_float(u);
}
__device__ __forceinline__ uint32_t cvt_tf32_u(uint32_t v) {
    uint32_t u;
    asm("cvt.rna.tf32.f32 %0, %1;" : "=r"(u) : "r"(v));
    return u;
}
__device__ __forceinline__ uint32_t smem_u32(const void* p) {
    uint32_t a;
    asm("{ .reg .u64 t; cvta.to.shared.u64 t, %1; cvt.u32.u64 %0, t; }" : "=r"(a) : "l"(p));
    return a;
}
#define CP_ASYNC16(dst, src) \
    asm volatile("cp.async.cg.shared.global [%0], [%1], 16;" :: "r"(dst), "l"(src) : "memory")
#define CP_COMMIT() asm volatile("cp.async.commit_group;" ::: "memory")
#define CP_WAIT(n)  asm volatile("cp.async.wait_group %0;" :: "n"(n) : "memory")

__device__ __forceinline__ void mma_tf32(float* d, const uint32_t* a, const uint32_t* b) {
    asm volatile(
        "mma.sync.aligned.m16n8k8.row.col.f32.tf32.tf32.f32 "
        "{%0,%1,%2,%3}, {%4,%5,%6,%7}, {%8,%9}, {%0,%1,%2,%3};"
        : "+f"(d[0]), "+f"(d[1]), "+f"(d[2]), "+f"(d[3])
        : "r"(a[0]), "r"(a[1]), "r"(a[2]), "r"(a[3]), "r"(b[0]), "r"(b[1]));
}
__device__ __forceinline__ void ldsm_x4(uint32_t* r, uint32_t addr) {
    asm volatile("ldmatrix.sync.aligned.m8n8.x4.shared.b16 {%0,%1,%2,%3}, [%4];"
        : "=r"(r[0]), "=r"(r[1]), "=r"(r[2]), "=r"(r[3]) : "r"(addr));
}

// ---------------------------------------------------------------------------
__global__ void k_init() {
    int i = threadIdx.x;
    if (i < EEXP) { g_count[i] = 0; g_cursor[i] = 0; }
}

// Gate: one warp per token.
__global__ void k_gate(const float* __restrict__ x, const float* __restrict__ Wg) {
    int t = blockIdx.x * 8 + (threadIdx.x >> 5);
    int lane = threadIdx.x & 31;
    const float* xr = x + (size_t)t * DDIM;

    float acc[EEXP];
#pragma unroll
    for (int e = 0; e < EEXP; e++) acc[e] = 0.f;
#pragma unroll 4
    for (int i = 0; i < DDIM / 32; i++) {
        int d = i * 32 + lane;
        float xv = xr[d];
        const float4* wr = (const float4*)(Wg + (size_t)d * EEXP);
        float4 w0 = wr[0], w1 = wr[1];
        acc[0] += xv * w0.x; acc[1] += xv * w0.y;
        acc[2] += xv * w0.z; acc[3] += xv * w0.w;
        acc[4] += xv * w1.x; acc[5] += xv * w1.y;
        acc[6] += xv * w1.z; acc[7] += xv * w1.w;
    }
#pragma unroll
    for (int off = 16; off > 0; off >>= 1)
#pragma unroll
        for (int e = 0; e < EEXP; e++)
            acc[e] += __shfl_xor_sync(0xffffffffu, acc[e], off);

    if (lane == 0) {
        int i1 = 0;
#pragma unroll
        for (int e = 1; e < EEXP; e++) if (acc[e] > acc[i1]) i1 = e;
        int i2 = -1;
#pragma unroll
        for (int e = 0; e < EEXP; e++) {
            if (e == i1) continue;
            if (i2 < 0 || acc[e] > acc[i2]) i2 = e;
        }
        float wa = 1.f / (1.f + expf(acc[i2] - acc[i1]));
        g_te[2 * t] = i1;  g_te[2 * t + 1] = i2;
        g_tw[2 * t] = wa;  g_tw[2 * t + 1] = 1.f - wa;
        atomicAdd(&g_count[i1], 1);
        atomicAdd(&g_count[i2], 1);
    }
}

__global__ void k_offs() {
    if (threadIdx.x == 0) {
        int o = 0;
#pragma unroll
        for (int e = 0; e < EEXP; e++) {
            g_offs[e] = o;
            o += (g_count[e] + SEGPAD - 1) & ~(SEGPAD - 1);
            g_cursor[e] = 0;
        }
        g_offs[EEXP] = o;
    }
}

// Gather + round to tf32 (RNA) so the MMA truncation is lossless.
__global__ void k_gather(const float* __restrict__ x) {
    int a = blockIdx.x * 8 + (threadIdx.x >> 5);
    int lane = threadIdx.x & 31;
    if (a >= NASSIGN) return;
    int t = a >> 1;
    int e = g_te[a];
    int slot = 0;
    if (lane == 0) {
        slot = g_offs[e] + atomicAdd(&g_cursor[e], 1);
        g_slot[a] = slot;
    }
    slot = __shfl_sync(0xffffffffu, slot, 0);
    const float4* src = (const float4*)(x + (size_t)t * DDIM);
    float4* dst = (float4*)(g_xp + (size_t)slot * DDIM);
#pragma unroll
    for (int i = 0; i < 8; i++) {
        float4 v = src[lane + 32 * i];
        v.x = to_tf32(v.x); v.y = to_tf32(v.y);
        v.z = to_tf32(v.z); v.w = to_tf32(v.w);
        dst[lane + 32 * i] = v;
    }
}

__global__ void k_zeropad() {
    int e = blockIdx.x;
    int start = g_offs[e] + g_count[e];
    int end = g_offs[e + 1];
    for (int r = start + (int)blockIdx.y; r < end; r += (int)gridDim.y) {
        float4* dst = (float4*)(g_xp + (size_t)r * DDIM);
        for (int i = threadIdx.x; i < DDIM / 4; i += 256)
            dst[i] = make_float4(0.f, 0.f, 0.f, 0.f);
    }
}

__device__ __forceinline__ float gelu_tanh(float v) {
    float v3 = v * v * v;
    return 0.5f * v * (1.f + tanhf(0.7978845608028654f * (v + 0.044715f * v3)));
}

// ---------------------------------------------------------------------------
// mma.sync tf32 GEMM: C[m][n] = A[m][k] * W[e][k][n] over padded segments.
// BM=128, BN=256, BK=64, 512 threads (16 warps, warp tile 64x32), 2 stages,
// single barrier per ktile.
#define BM 128
#define BN 256
#define BKF 64
#define NSTAGE 2
#define ASTRIDE 68
#define BSTRIDE 264
#define AS_ELEMS (BM * ASTRIDE)    // 8704
#define BS_ELEMS (BKF * BSTRIDE)   // 16896
#define SMEM_GEMM (NSTAGE * (AS_ELEMS + BS_ELEMS) * 4)  // 204800

__global__ __launch_bounds__(512, 1)
void k_gemm_mma(const float* __restrict__ W, int K, int Ntot, int doGelu) {
    int row0 = blockIdx.x * BM;
    if (row0 >= g_offs[EEXP]) return;
    int e = 0;
    while (g_offs[e + 1] <= row0) e++;

    extern __shared__ float smem[];
    float* Bs = smem + NSTAGE * AS_ELEMS;  // [NSTAGE][BKF][BSTRIDE]

    int tid = threadIdx.x, wid = tid >> 5, lane = tid & 31;
    int gid = lane >> 2, tig = lane & 3;
    int warp_m = wid & 1, warp_n = wid >> 1;   // 2 x 8 warps, tile 64x32

    const float* A = doGelu ? g_xp : g_h;
    float* C       = doGelu ? g_h  : g_y;
    const float* B = W + (size_t)e * K * Ntot + (size_t)blockIdx.y * BN;

    // A loader: 128x64 floats = 2048 16B chunks, 4/thread.
    int ar = tid >> 4, ac = (tid & 15) * 4;      // rows ar, ar+32, ar+64, ar+96
    // B loader: 64x256 floats = 4096 chunks, 8/thread.
    int br = tid >> 6, bc = (tid & 63) * 4;      // rows br + i*8, i=0..7

    const float* asrc = A + (size_t)(row0 + ar) * K + ac;
    const float* bsrc = B + (size_t)br * Ntot + bc;

    uint32_t sbase = smem_u32(smem);
    uint32_t a_d = sbase + ((uint32_t)ar * ASTRIDE + ac) * 4;
    uint32_t b_d = sbase + (uint32_t)NSTAGE * AS_ELEMS * 4 + ((uint32_t)br * BSTRIDE + bc) * 4;

    // ldmatrix per-lane base: row = lane&15 within 16-row tile, col = (lane>>4)*4.
    uint32_t lm_base = sbase +
        (((uint32_t)(warp_m * 64 + (lane & 15))) * ASTRIDE + ((lane >> 4) << 2)) * 4;

    float acc[4][4][4];
#pragma unroll
    for (int mt = 0; mt < 4; mt++)
#pragma unroll
        for (int nt = 0; nt < 4; nt++)
#pragma unroll
            for (int j = 0; j < 4; j++) acc[mt][nt][j] = 0.f;

    int KT = K / BKF;   // 16 (GEMM1) or 64 (GEMM2)

#define LOAD_TILE(kt, st) do { \
    int _k0 = (kt) * BKF; \
    uint32_t _ao = (uint32_t)(st) * AS_ELEMS * 4; \
    uint32_t _bo = (uint32_t)(st) * BS_ELEMS * 4; \
    CP_ASYNC16(a_d + _ao,                        asrc + _k0); \
    CP_ASYNC16(a_d + _ao + 32u * ASTRIDE * 4,    asrc + _k0 + (size_t)32 * K); \
    CP_ASYNC16(a_d + _ao + 64u * ASTRIDE * 4,    asrc + _k0 + (size_t)64 * K); \
    CP_ASYNC16(a_d + _ao + 96u * ASTRIDE * 4,    asrc + _k0 + (size_t)96 * K); \
    CP_ASYNC16(b_d + _bo,                        bsrc + (size_t)_k0 * Ntot); \
    CP_ASYNC16(b_d + _bo +  8u * BSTRIDE * 4,    bsrc + (size_t)(_k0 +  8) * Ntot); \
    CP_ASYNC16(b_d + _bo + 16u * BSTRIDE * 4,    bsrc + (size_t)(_k0 + 16) * Ntot); \
    CP_ASYNC16(b_d + _bo + 24u * BSTRIDE * 4,    bsrc + (size_t)(_k0 + 24) * Ntot); \
    CP_ASYNC16(b_d + _bo + 32u * BSTRIDE * 4,    bsrc + (size_t)(_k0 + 32) * Ntot); \
    CP_ASYNC16(b_d + _bo + 40u * BSTRIDE * 4,    bsrc + (size_t)(_k0 + 40) * Ntot); \
    CP_ASYNC16(b_d + _bo + 48u * BSTRIDE * 4,    bsrc + (size_t)(_k0 + 48) * Ntot); \
    CP_ASYNC16(b_d + _bo + 56u * BSTRIDE * 4,    bsrc + (size_t)(_k0 + 56) * Ntot); \
} while (0)

    // prologue: tile 0 -> stage 0
    LOAD_TILE(0, 0); CP_COMMIT();

    for (int kt = 0; kt < KT; kt++) {
        int stage = kt & 1;
        CP_WAIT(0);          // tile kt resident
        __syncthreads();     // all warps done reading stage kt-1 (== stage kt+1)
        if (kt + 1 < KT) {
            LOAD_TILE(kt + 1, stage ^ 1);
            CP_COMMIT();
        }

        uint32_t a_lm = lm_base + (uint32_t)stage * AS_ELEMS * 4;
        const float* bt = Bs + stage * BS_ELEMS + tig * BSTRIDE + warp_n * 32 + gid;
#pragma unroll
        for (int ks = 0; ks < 8; ks++) {
            int k0 = ks * 8;
            uint32_t afrag[4][4];
#pragma unroll
            for (int mt = 0; mt < 4; mt++)
                ldsm_x4(afrag[mt], a_lm + ((uint32_t)mt * 16 * ASTRIDE + k0) * 4);
            uint32_t bfrag[4][2];
#pragma unroll
            for (int nt = 0; nt < 4; nt++) {
                const float* bp = bt + (size_t)k0 * BSTRIDE + nt * 8;
                bfrag[nt][0] = cvt_tf32_u(__float_as_uint(bp[0]));
                bfrag[nt][1] = cvt_tf32_u(__float_as_uint(bp[4 * BSTRIDE]));
            }
#pragma unroll
            for (int mt = 0; mt < 4; mt++)
#pragma unroll
                for (int nt = 0; nt < 4; nt++)
                    mma_tf32(acc[mt][nt], afrag[mt], bfrag[nt]);
        }
    }

    // epilogue
#pragma unroll
    for (int mt = 0; mt < 4; mt++) {
        int mrow = row0 + warp_m * 64 + mt * 16 + gid;
#pragma unroll
        for (int nt = 0; nt < 4; nt++) {
            int col = blockIdx.y * BN + warp_n * 32 + nt * 8 + 2 * tig;
            float2 v0 = make_float2(acc[mt][nt][0], acc[mt][nt][1]);
            float2 v1 = make_float2(acc[mt][nt][2], acc[mt][nt][3]);
            if (doGelu) {
                v0.x = to_tf32(gelu_tanh(v0.x)); v0.y = to_tf32(gelu_tanh(v0.y));
                v1.x = to_tf32(gelu_tanh(v1.x)); v1.y = to_tf32(gelu_tanh(v1.y));
            }
            *(float2*)(C + (size_t)mrow * Ntot + col) = v0;
            *(float2*)(C + (size_t)(mrow + 8) * Ntot + col) = v1;
        }
    }
}

__global__ void k_combine(float* __restrict__ out) {
    int t = blockIdx.x * 8 + (threadIdx.x >> 5);
    int lane = threadIdx.x & 31;
    if (t >= T_TOK) return;
    int a0 = g_slot[2 * t], a1 = g_slot[2 * t + 1];
    float w0 = g_tw[2 * t], w1 = g_tw[2 * t + 1];
    const float4* y0 = (const float4*)(g_y + (size_t)a0 * DDIM);
    const float4* y1 = (const float4*)(g_y + (size_t)a1 * DDIM);
    float4* o = (float4*)(out + (size_t)t * DDIM);
#pragma unroll
    for (int i = 0; i < 8; i++) {
        int idx = lane + 32 * i;
        float4 p = y0[idx], q = y1[idx];
        o[idx] = make_float4(w0 * p.x + w1 * q.x, w0 * p.y + w1 * q.y,
                             w0 * p.z + w1 * q.z, w0 * p.w + w1 * q.w);
    }
}

// ---------------------------------------------------------------------------
extern "C" void kernel_launch(void* const* d_in, const int* in_sizes, int n_in,
                              void* d_out, int out_size) {
    const float* x  = (const float*)d_in[0];
    const float* Wg = (const float*)d_in[1];
    const float* w1 = (const float*)d_in[2];
    const float* w2 = (const float*)d_in[3];
    float* out = (float*)d_out;

    cudaFuncSetAttribute(k_gemm_mma, cudaFuncAttributeMaxDynamicSharedMemorySize, SMEM_GEMM);

    k_init<<<1, 32>>>();
    k_gate<<<T_TOK / 8, 256>>>(x, Wg);
    k_offs<<<1, 32>>>();
    k_gather<<<NASSIGN / 8, 256>>>(x);
    k_zeropad<<<dim3(EEXP, 8), 256>>>();

    dim3 grid1(MAXSLOTS / BM, FDIM / BN);   // (136, 16)
    k_gemm_mma<<<grid1, 512, SMEM_GEMM>>>(w1, DDIM, FDIM, 1);

    dim3 grid2(MAXSLOTS / BM, DDIM / BN);   // (136, 4)
    k_gemm_mma<<<grid2, 512, SMEM_GEMM>>>(w2, FDIM, DDIM, 0);

    k_combine<<<T_TOK / 8, 256>>>(out);
}

// round 9
// speedup vs baseline: 2.6861x; 1.7134x over previous
#include <cuda_runtime.h>
#include <cuda_fp16.h>
#include <cstdint>

// ---------------------------------------------------------------------------
// MoE layer: B=4,S=2048,D=1024,E=8,F=4096, top-k=2
// Round 8: fp16 mma.sync m16n8k16 (2x MAC/instr vs tf32), ldmatrix(+trans)
// fragments, fp16 activations/weights (11-bit significand == tf32), fp32 accum.
// ---------------------------------------------------------------------------

#define T_TOK   8192
#define DDIM    1024
#define EEXP    8
#define FDIM    4096
#define NASSIGN (T_TOK * 2)
#define SEGPAD  128
#define MAXSLOTS (NASSIGN + EEXP * SEGPAD)  // 17408

__device__ __half g_xph[MAXSLOTS * (size_t)DDIM];
__device__ __half g_h  [MAXSLOTS * (size_t)FDIM];
__device__ float  g_y  [MAXSLOTS * (size_t)DDIM];
__device__ __half g_w1h[(size_t)EEXP * DDIM * FDIM];
__device__ __half g_w2h[(size_t)EEXP * FDIM * DDIM];
__device__ int   g_te[NASSIGN];
__device__ float g_tw[NASSIGN];
__device__ int   g_slot[NASSIGN];
__device__ int   g_count[EEXP];
__device__ int   g_cursor[EEXP];
__device__ int   g_offs[EEXP + 1];

__device__ __forceinline__ uint32_t smem_u32(const void* p) {
    uint32_t a;
    asm("{ .reg .u64 t; cvta.to.shared.u64 t, %1; cvt.u32.u64 %0, t; }" : "=r"(a) : "l"(p));
    return a;
}
#define CP_ASYNC16(dst, src) \
    asm volatile("cp.async.cg.shared.global [%0], [%1], 16;" :: "r"(dst), "l"(src) : "memory")
#define CP_COMMIT() asm volatile("cp.async.commit_group;" ::: "memory")
#define CP_WAIT(n)  asm volatile("cp.async.wait_group %0;" :: "n"(n) : "memory")

__device__ __forceinline__ void mma_f16(float* d, const uint32_t* a, const uint32_t* b) {
    asm volatile(
        "mma.sync.aligned.m16n8k16.row.col.f32.f16.f16.f32 "
        "{%0,%1,%2,%3}, {%4,%5,%6,%7}, {%8,%9}, {%0,%1,%2,%3};"
        : "+f"(d[0]), "+f"(d[1]), "+f"(d[2]), "+f"(d[3])
        : "r"(a[0]), "r"(a[1]), "r"(a[2]), "r"(a[3]), "r"(b[0]), "r"(b[1]));
}
__device__ __forceinline__ void ldsm_x4(uint32_t* r, uint32_t addr) {
    asm volatile("ldmatrix.sync.aligned.m8n8.x4.shared.b16 {%0,%1,%2,%3}, [%4];"
        : "=r"(r[0]), "=r"(r[1]), "=r"(r[2]), "=r"(r[3]) : "r"(addr));
}
__device__ __forceinline__ void ldsm_x4_t(uint32_t* r, uint32_t addr) {
    asm volatile("ldmatrix.sync.aligned.m8n8.x4.trans.shared.b16 {%0,%1,%2,%3}, [%4];"
        : "=r"(r[0]), "=r"(r[1]), "=r"(r[2]), "=r"(r[3]) : "r"(addr));
}

// ---------------------------------------------------------------------------
__global__ void k_init() {
    int i = threadIdx.x;
    if (i < EEXP) { g_count[i] = 0; g_cursor[i] = 0; }
}

// Gate: one warp per token (fp32, unchanged).
__global__ void k_gate(const float* __restrict__ x, const float* __restrict__ Wg) {
    int t = blockIdx.x * 8 + (threadIdx.x >> 5);
    int lane = threadIdx.x & 31;
    const float* xr = x + (size_t)t * DDIM;

    float acc[EEXP];
#pragma unroll
    for (int e = 0; e < EEXP; e++) acc[e] = 0.f;
#pragma unroll 4
    for (int i = 0; i < DDIM / 32; i++) {
        int d = i * 32 + lane;
        float xv = xr[d];
        const float4* wr = (const float4*)(Wg + (size_t)d * EEXP);
        float4 w0 = wr[0], w1 = wr[1];
        acc[0] += xv * w0.x; acc[1] += xv * w0.y;
        acc[2] += xv * w0.z; acc[3] += xv * w0.w;
        acc[4] += xv * w1.x; acc[5] += xv * w1.y;
        acc[6] += xv * w1.z; acc[7] += xv * w1.w;
    }
#pragma unroll
    for (int off = 16; off > 0; off >>= 1)
#pragma unroll
        for (int e = 0; e < EEXP; e++)
            acc[e] += __shfl_xor_sync(0xffffffffu, acc[e], off);

    if (lane == 0) {
        int i1 = 0;
#pragma unroll
        for (int e = 1; e < EEXP; e++) if (acc[e] > acc[i1]) i1 = e;
        int i2 = -1;
#pragma unroll
        for (int e = 0; e < EEXP; e++) {
            if (e == i1) continue;
            if (i2 < 0 || acc[e] > acc[i2]) i2 = e;
        }
        float wa = 1.f / (1.f + expf(acc[i2] - acc[i1]));
        g_te[2 * t] = i1;  g_te[2 * t + 1] = i2;
        g_tw[2 * t] = wa;  g_tw[2 * t + 1] = 1.f - wa;
        atomicAdd(&g_count[i1], 1);
        atomicAdd(&g_count[i2], 1);
    }
}

__global__ void k_offs() {
    if (threadIdx.x == 0) {
        int o = 0;
#pragma unroll
        for (int e = 0; e < EEXP; e++) {
            g_offs[e] = o;
            o += (g_count[e] + SEGPAD - 1) & ~(SEGPAD - 1);
            g_cursor[e] = 0;
        }
        g_offs[EEXP] = o;
    }
}

// Convert fp32 weights -> fp16 (RN).
__global__ void k_cvt(const float4* __restrict__ src, uint2* __restrict__ dst) {
    int i = blockIdx.x * 256 + threadIdx.x;
    float4 v = src[i];
    __half2 h01 = __floats2half2_rn(v.x, v.y);
    __half2 h23 = __floats2half2_rn(v.z, v.w);
    uint2 u;
    u.x = *(uint32_t*)&h01;
    u.y = *(uint32_t*)&h23;
    dst[i] = u;
}

// Gather: permute + convert x row to fp16.
__global__ void k_gather(const float* __restrict__ x) {
    int a = blockIdx.x * 8 + (threadIdx.x >> 5);
    int lane = threadIdx.x & 31;
    if (a >= NASSIGN) return;
    int t = a >> 1;
    int e = g_te[a];
    int slot = 0;
    if (lane == 0) {
        slot = g_offs[e] + atomicAdd(&g_cursor[e], 1);
        g_slot[a] = slot;
    }
    slot = __shfl_sync(0xffffffffu, slot, 0);
    const float4* src = (const float4*)(x + (size_t)t * DDIM);
    uint2* dst = (uint2*)(g_xph + (size_t)slot * DDIM);
#pragma unroll
    for (int i = 0; i < 8; i++) {
        float4 v = src[lane + 32 * i];
        __half2 h01 = __floats2half2_rn(v.x, v.y);
        __half2 h23 = __floats2half2_rn(v.z, v.w);
        uint2 u;
        u.x = *(uint32_t*)&h01;
        u.y = *(uint32_t*)&h23;
        dst[lane + 32 * i] = u;
    }
}

__global__ void k_zeropad() {
    int e = blockIdx.x;
    int start = g_offs[e] + g_count[e];
    int end = g_offs[e + 1];
    for (int r = start + (int)blockIdx.y; r < end; r += (int)gridDim.y) {
        uint4* dst = (uint4*)(g_xph + (size_t)r * DDIM);
        for (int i = threadIdx.x; i < DDIM * 2 / 16; i += 256)
            dst[i] = make_uint4(0, 0, 0, 0);
    }
}

__device__ __forceinline__ float gelu_tanh(float v) {
    float v3 = v * v * v;
    return 0.5f * v * (1.f + tanhf(0.7978845608028654f * (v + 0.044715f * v3)));
}

// ---------------------------------------------------------------------------
// fp16 mma GEMM: C[m][n] = A[m][k] * W[e][k][n] over padded expert segments.
// BM=128, BN=256, BK=64 halves, 512 threads (16 warps, warp tile 64x32),
// 2 stages, 1 barrier/ktile. A row stride 144B, B row stride 528B
// (+16B/row mod 128 -> every ldmatrix phase conflict-free).
#define BM 128
#define BN 256
#define BKF 64
#define NSTAGE 2
#define ASTR 72                      // halves per A smem row (144 B)
#define BSTR 264                     // halves per B smem row (528 B)
#define ATILE_B (BM * ASTR * 2)      // 18432 B
#define BTILE_B (BKF * BSTR * 2)     // 33792 B
#define SMEM_GEMM (NSTAGE * (ATILE_B + BTILE_B))  // 104448 B

__global__ __launch_bounds__(512, 1)
void k_gemm_h(const __half* __restrict__ A, const __half* __restrict__ W,
              int K, int Ntot, int doGelu) {
    int row0 = blockIdx.x * BM;
    if (row0 >= g_offs[EEXP]) return;
    int e = 0;
    while (g_offs[e + 1] <= row0) e++;

    extern __shared__ char smem[];
    uint32_t sbase = smem_u32(smem);

    int tid = threadIdx.x, wid = tid >> 5, lane = tid & 31;
    int gid = lane >> 2, tig = lane & 3;
    int warp_m = wid & 1, warp_n = wid >> 1;   // 2 x 8 warps, warp tile 64x32

    const __half* B = W + (size_t)e * K * Ntot + (size_t)blockIdx.y * BN;

    // A loader: 128 rows x 64 halves (128B/row) = 1024 chunks, 2/thread.
    int ar = tid >> 3, ach = tid & 7;
    const __half* asrc = A + (size_t)(row0 + ar) * K + ach * 8;
    uint32_t a_d = sbase + (uint32_t)ar * 144 + (uint32_t)ach * 16;
    // B loader: 64 rows x 256 halves (512B/row) = 2048 chunks, 4/thread.
    int br = tid >> 3, bch = tid & 7;
    const __half* bsrc = B + (size_t)br * Ntot + bch * 8;
    uint32_t b_d = sbase + (uint32_t)NSTAGE * ATILE_B + (uint32_t)br * 528 + (uint32_t)bch * 16;

    // ldmatrix A: lanes 0-15 rows m0-15 (k halves 0-7), lanes 16-31 same rows k 8-15.
    uint32_t a_lm = sbase + ((uint32_t)(warp_m * 64 + (lane & 15))) * 144 + ((lane >> 4) << 4);
    // ldmatrix B (trans): lane -> k row (lane&7) + ((lane>>3)&1)*8, n offset (lane>>4)*8.
    uint32_t b_row = (lane & 7) + ((lane >> 3) & 1) * 8;
    uint32_t b_ncol = (uint32_t)(warp_n * 32) + ((lane >> 4) << 3);
    uint32_t b_lm = sbase + (uint32_t)NSTAGE * ATILE_B + b_row * 528 + b_ncol * 2;

    float acc[4][4][4];
#pragma unroll
    for (int mt = 0; mt < 4; mt++)
#pragma unroll
        for (int nt = 0; nt < 4; nt++)
#pragma unroll
            for (int j = 0; j < 4; j++) acc[mt][nt][j] = 0.f;

    int KT = K / BKF;   // 16 (GEMM1) or 64 (GEMM2)

#define LOAD_TILE(kt, st) do { \
    int _k0 = (kt) * BKF; \
    uint32_t _ao = (uint32_t)(st) * ATILE_B; \
    uint32_t _bo = (uint32_t)(st) * BTILE_B; \
    CP_ASYNC16(a_d + _ao,                  asrc + _k0); \
    CP_ASYNC16(a_d + _ao + 64u * 144,      asrc + _k0 + (size_t)64 * K); \
    CP_ASYNC16(b_d + _bo,                  bsrc + (size_t)_k0 * Ntot); \
    CP_ASYNC16(b_d + _bo + 128u,           bsrc + (size_t)_k0 * Ntot + 64); \
    CP_ASYNC16(b_d + _bo + 256u,           bsrc + (size_t)_k0 * Ntot + 128); \
    CP_ASYNC16(b_d + _bo + 384u,           bsrc + (size_t)_k0 * Ntot + 192); \
} while (0)

    LOAD_TILE(0, 0); CP_COMMIT();

    for (int kt = 0; kt < KT; kt++) {
        int stage = kt & 1;
        CP_WAIT(0);
        __syncthreads();
        if (kt + 1 < KT) {
            LOAD_TILE(kt + 1, stage ^ 1);
            CP_COMMIT();
        }

        uint32_t a_s = a_lm + (uint32_t)stage * ATILE_B;
        uint32_t b_s = b_lm + (uint32_t)stage * BTILE_B;
#pragma unroll
        for (int ks = 0; ks < 4; ks++) {   // 4 x k16 = BK 64
            uint32_t afrag[4][4];
#pragma unroll
            for (int mt = 0; mt < 4; mt++)
                ldsm_x4(afrag[mt], a_s + (uint32_t)mt * 16 * 144 + (uint32_t)ks * 32);
            uint32_t bfrag[4][2];
#pragma unroll
            for (int nt2 = 0; nt2 < 2; nt2++) {
                uint32_t r[4];
                ldsm_x4_t(r, b_s + (uint32_t)ks * 16 * 528 + (uint32_t)nt2 * 32);
                bfrag[2 * nt2][0] = r[0]; bfrag[2 * nt2][1] = r[1];
                bfrag[2 * nt2 + 1][0] = r[2]; bfrag[2 * nt2 + 1][1] = r[3];
            }
#pragma unroll
            for (int mt = 0; mt < 4; mt++)
#pragma unroll
                for (int nt = 0; nt < 4; nt++)
                    mma_f16(acc[mt][nt], afrag[mt], bfrag[nt]);
        }
    }

    // epilogue
#pragma unroll
    for (int mt = 0; mt < 4; mt++) {
        int mrow = row0 + warp_m * 64 + mt * 16 + gid;
#pragma unroll
        for (int nt = 0; nt < 4; nt++) {
            int col = blockIdx.y * BN + warp_n * 32 + nt * 8 + 2 * tig;
            if (doGelu) {
                __half2 h0 = __floats2half2_rn(gelu_tanh(acc[mt][nt][0]),
                                               gelu_tanh(acc[mt][nt][1]));
                __half2 h1 = __floats2half2_rn(gelu_tanh(acc[mt][nt][2]),
                                               gelu_tanh(acc[mt][nt][3]));
                *(__half2*)(g_h + (size_t)mrow * Ntot + col) = h0;
                *(__half2*)(g_h + (size_t)(mrow + 8) * Ntot + col) = h1;
            } else {
                *(float2*)(g_y + (size_t)mrow * Ntot + col) =
                    make_float2(acc[mt][nt][0], acc[mt][nt][1]);
                *(float2*)(g_y + (size_t)(mrow + 8) * Ntot + col) =
                    make_float2(acc[mt][nt][2], acc[mt][nt][3]);
            }
        }
    }
}

__global__ void k_combine(float* __restrict__ out) {
    int t = blockIdx.x * 8 + (threadIdx.x >> 5);
    int lane = threadIdx.x & 31;
    if (t >= T_TOK) return;
    int a0 = g_slot[2 * t], a1 = g_slot[2 * t + 1];
    float w0 = g_tw[2 * t], w1 = g_tw[2 * t + 1];
    const float4* y0 = (const float4*)(g_y + (size_t)a0 * DDIM);
    const float4* y1 = (const float4*)(g_y + (size_t)a1 * DDIM);
    float4* o = (float4*)(out + (size_t)t * DDIM);
#pragma unroll
    for (int i = 0; i < 8; i++) {
        int idx = lane + 32 * i;
        float4 p = y0[idx], q = y1[idx];
        o[idx] = make_float4(w0 * p.x + w1 * q.x, w0 * p.y + w1 * q.y,
                             w0 * p.z + w1 * q.z, w0 * p.w + w1 * q.w);
    }
}

// ---------------------------------------------------------------------------
extern "C" void kernel_launch(void* const* d_in, const int* in_sizes, int n_in,
                              void* d_out, int out_size) {
    const float* x  = (const float*)d_in[0];
    const float* Wg = (const float*)d_in[1];
    const float* w1 = (const float*)d_in[2];
    const float* w2 = (const float*)d_in[3];
    float* out = (float*)d_out;

    cudaFuncSetAttribute(k_gemm_h, cudaFuncAttributeMaxDynamicSharedMemorySize, SMEM_GEMM);

    __half* w1h; cudaGetSymbolAddress((void**)&w1h, g_w1h);
    __half* w2h; cudaGetSymbolAddress((void**)&w2h, g_w2h);
    __half* xph; cudaGetSymbolAddress((void**)&xph, g_xph);
    __half* hbuf; cudaGetSymbolAddress((void**)&hbuf, g_h);

    k_init<<<1, 32>>>();
    k_gate<<<T_TOK / 8, 256>>>(x, Wg);
    k_offs<<<1, 32>>>();

    int n4 = EEXP * DDIM * FDIM / 4;   // 8388608 float4 per weight
    k_cvt<<<n4 / 256, 256>>>((const float4*)w1, (uint2*)w1h);
    k_cvt<<<n4 / 256, 256>>>((const float4*)w2, (uint2*)w2h);

    k_gather<<<NASSIGN / 8, 256>>>(x);
    k_zeropad<<<dim3(EEXP, 8), 256>>>();

    dim3 grid1(MAXSLOTS / BM, FDIM / BN);   // (136, 16)
    k_gemm_h<<<grid1, 512, SMEM_GEMM>>>(xph, w1h, DDIM, FDIM, 1);

    dim3 grid2(MAXSLOTS / BM, DDIM / BN);   // (136, 4)
    k_gemm_h<<<grid2, 512, SMEM_GEMM>>>(hbuf, w2h, FDIM, DDIM, 0);

    k_combine<<<T_TOK / 8, 256>>>(out);
}

// round 10
// speedup vs baseline: 2.8268x; 1.0524x over previous
#include <cuda_runtime.h>
#include <cuda_fp16.h>
#include <cstdint>

// ---------------------------------------------------------------------------
// MoE layer: B=4,S=2048,D=1024,E=8,F=4096, top-k=2
// Round 9: fp16 mma m16n8k16 + register fragment double-buffering (prefetch
// ks+1 ldsm before mma of ks).
// ---------------------------------------------------------------------------

#define T_TOK   8192
#define DDIM    1024
#define EEXP    8
#define FDIM    4096
#define NASSIGN (T_TOK * 2)
#define SEGPAD  128
#define MAXSLOTS (NASSIGN + EEXP * SEGPAD)  // 17408

__device__ __half g_xph[MAXSLOTS * (size_t)DDIM];
__device__ __half g_h  [MAXSLOTS * (size_t)FDIM];
__device__ float  g_y  [MAXSLOTS * (size_t)DDIM];
__device__ __half g_w1h[(size_t)EEXP * DDIM * FDIM];
__device__ __half g_w2h[(size_t)EEXP * FDIM * DDIM];
__device__ int   g_te[NASSIGN];
__device__ float g_tw[NASSIGN];
__device__ int   g_slot[NASSIGN];
__device__ int   g_count[EEXP];
__device__ int   g_cursor[EEXP];
__device__ int   g_offs[EEXP + 1];

__device__ __forceinline__ uint32_t smem_u32(const void* p) {
    uint32_t a;
    asm("{ .reg .u64 t; cvta.to.shared.u64 t, %1; cvt.u32.u64 %0, t; }" : "=r"(a) : "l"(p));
    return a;
}
#define CP_ASYNC16(dst, src) \
    asm volatile("cp.async.cg.shared.global [%0], [%1], 16;" :: "r"(dst), "l"(src) : "memory")
#define CP_COMMIT() asm volatile("cp.async.commit_group;" ::: "memory")
#define CP_WAIT(n)  asm volatile("cp.async.wait_group %0;" :: "n"(n) : "memory")

__device__ __forceinline__ void mma_f16(float* d, const uint32_t* a, const uint32_t* b) {
    asm volatile(
        "mma.sync.aligned.m16n8k16.row.col.f32.f16.f16.f32 "
        "{%0,%1,%2,%3}, {%4,%5,%6,%7}, {%8,%9}, {%0,%1,%2,%3};"
        : "+f"(d[0]), "+f"(d[1]), "+f"(d[2]), "+f"(d[3])
        : "r"(a[0]), "r"(a[1]), "r"(a[2]), "r"(a[3]), "r"(b[0]), "r"(b[1]));
}
__device__ __forceinline__ void ldsm_x4(uint32_t* r, uint32_t addr) {
    asm volatile("ldmatrix.sync.aligned.m8n8.x4.shared.b16 {%0,%1,%2,%3}, [%4];"
        : "=r"(r[0]), "=r"(r[1]), "=r"(r[2]), "=r"(r[3]) : "r"(addr));
}
__device__ __forceinline__ void ldsm_x4_t(uint32_t* r, uint32_t addr) {
    asm volatile("ldmatrix.sync.aligned.m8n8.x4.trans.shared.b16 {%0,%1,%2,%3}, [%4];"
        : "=r"(r[0]), "=r"(r[1]), "=r"(r[2]), "=r"(r[3]) : "r"(addr));
}

// ---------------------------------------------------------------------------
__global__ void k_init() {
    int i = threadIdx.x;
    if (i < EEXP) { g_count[i] = 0; g_cursor[i] = 0; }
}

// Gate: one warp per token (fp32).
__global__ void k_gate(const float* __restrict__ x, const float* __restrict__ Wg) {
    int t = blockIdx.x * 8 + (threadIdx.x >> 5);
    int lane = threadIdx.x & 31;
    const float* xr = x + (size_t)t * DDIM;

    float acc[EEXP];
#pragma unroll
    for (int e = 0; e < EEXP; e++) acc[e] = 0.f;
#pragma unroll 4
    for (int i = 0; i < DDIM / 32; i++) {
        int d = i * 32 + lane;
        float xv = xr[d];
        const float4* wr = (const float4*)(Wg + (size_t)d * EEXP);
        float4 w0 = wr[0], w1 = wr[1];
        acc[0] += xv * w0.x; acc[1] += xv * w0.y;
        acc[2] += xv * w0.z; acc[3] += xv * w0.w;
        acc[4] += xv * w1.x; acc[5] += xv * w1.y;
        acc[6] += xv * w1.z; acc[7] += xv * w1.w;
    }
#pragma unroll
    for (int off = 16; off > 0; off >>= 1)
#pragma unroll
        for (int e = 0; e < EEXP; e++)
            acc[e] += __shfl_xor_sync(0xffffffffu, acc[e], off);

    if (lane == 0) {
        int i1 = 0;
#pragma unroll
        for (int e = 1; e < EEXP; e++) if (acc[e] > acc[i1]) i1 = e;
        int i2 = -1;
#pragma unroll
        for (int e = 0; e < EEXP; e++) {
            if (e == i1) continue;
            if (i2 < 0 || acc[e] > acc[i2]) i2 = e;
        }
        float wa = 1.f / (1.f + expf(acc[i2] - acc[i1]));
        g_te[2 * t] = i1;  g_te[2 * t + 1] = i2;
        g_tw[2 * t] = wa;  g_tw[2 * t + 1] = 1.f - wa;
        atomicAdd(&g_count[i1], 1);
        atomicAdd(&g_count[i2], 1);
    }
}

__global__ void k_offs() {
    if (threadIdx.x == 0) {
        int o = 0;
#pragma unroll
        for (int e = 0; e < EEXP; e++) {
            g_offs[e] = o;
            o += (g_count[e] + SEGPAD - 1) & ~(SEGPAD - 1);
            g_cursor[e] = 0;
        }
        g_offs[EEXP] = o;
    }
}

// Convert fp32 weights -> fp16 (RN).
__global__ void k_cvt(const float4* __restrict__ src, uint2* __restrict__ dst) {
    int i = blockIdx.x * 256 + threadIdx.x;
    float4 v = src[i];
    __half2 h01 = __floats2half2_rn(v.x, v.y);
    __half2 h23 = __floats2half2_rn(v.z, v.w);
    uint2 u;
    u.x = *(uint32_t*)&h01;
    u.y = *(uint32_t*)&h23;
    dst[i] = u;
}

// Gather: permute + convert x row to fp16.
__global__ void k_gather(const float* __restrict__ x) {
    int a = blockIdx.x * 8 + (threadIdx.x >> 5);
    int lane = threadIdx.x & 31;
    if (a >= NASSIGN) return;
    int t = a >> 1;
    int e = g_te[a];
    int slot = 0;
    if (lane == 0) {
        slot = g_offs[e] + atomicAdd(&g_cursor[e], 1);
        g_slot[a] = slot;
    }
    slot = __shfl_sync(0xffffffffu, slot, 0);
    const float4* src = (const float4*)(x + (size_t)t * DDIM);
    uint2* dst = (uint2*)(g_xph + (size_t)slot * DDIM);
#pragma unroll
    for (int i = 0; i < 8; i++) {
        float4 v = src[lane + 32 * i];
        __half2 h01 = __floats2half2_rn(v.x, v.y);
        __half2 h23 = __floats2half2_rn(v.z, v.w);
        uint2 u;
        u.x = *(uint32_t*)&h01;
        u.y = *(uint32_t*)&h23;
        dst[lane + 32 * i] = u;
    }
}

__global__ void k_zeropad() {
    int e = blockIdx.x;
    int start = g_offs[e] + g_count[e];
    int end = g_offs[e + 1];
    for (int r = start + (int)blockIdx.y; r < end; r += (int)gridDim.y) {
        uint4* dst = (uint4*)(g_xph + (size_t)r * DDIM);
        for (int i = threadIdx.x; i < DDIM * 2 / 16; i += 256)
            dst[i] = make_uint4(0, 0, 0, 0);
    }
}

__device__ __forceinline__ float gelu_tanh(float v) {
    float v3 = v * v * v;
    return 0.5f * v * (1.f + tanhf(0.7978845608028654f * (v + 0.044715f * v3)));
}

// ---------------------------------------------------------------------------
// fp16 mma GEMM with fragment double-buffering.
// BM=128, BN=256, BK=64 halves, 512 threads, 2 smem stages, 1 barrier/ktile.
#define BM 128
#define BN 256
#define BKF 64
#define NSTAGE 2
#define ATILE_B (BM * 72 * 2)        // 18432 B (A row stride 144 B)
#define BTILE_B (BKF * 264 * 2)      // 33792 B (B row stride 528 B)
#define SMEM_GEMM (NSTAGE * (ATILE_B + BTILE_B))  // 104448 B

__global__ __launch_bounds__(512, 1)
void k_gemm_h(const __half* __restrict__ A, const __half* __restrict__ W,
              int K, int Ntot, int doGelu) {
    int row0 = blockIdx.x * BM;
    if (row0 >= g_offs[EEXP]) return;
    int e = 0;
    while (g_offs[e + 1] <= row0) e++;

    extern __shared__ char smem[];
    uint32_t sbase = smem_u32(smem);

    int tid = threadIdx.x, wid = tid >> 5, lane = tid & 31;
    int gid = lane >> 2, tig = lane & 3;
    int warp_m = wid & 1, warp_n = wid >> 1;   // 2 x 8 warps, warp tile 64x32

    const __half* B = W + (size_t)e * K * Ntot + (size_t)blockIdx.y * BN;

    int ar = tid >> 3, ach = tid & 7;
    const __half* asrc = A + (size_t)(row0 + ar) * K + ach * 8;
    uint32_t a_d = sbase + (uint32_t)ar * 144 + (uint32_t)ach * 16;
    int br = tid >> 3, bch = tid & 7;
    const __half* bsrc = B + (size_t)br * Ntot + bch * 8;
    uint32_t b_d = sbase + (uint32_t)NSTAGE * ATILE_B + (uint32_t)br * 528 + (uint32_t)bch * 16;

    uint32_t a_lm = sbase + ((uint32_t)(warp_m * 64 + (lane & 15))) * 144 + ((lane >> 4) << 4);
    uint32_t b_row = (lane & 7) + ((lane >> 3) & 1) * 8;
    uint32_t b_ncol = (uint32_t)(warp_n * 32) + ((lane >> 4) << 3);
    uint32_t b_lm = sbase + (uint32_t)NSTAGE * ATILE_B + b_row * 528 + b_ncol * 2;

    float acc[4][4][4];
#pragma unroll
    for (int mt = 0; mt < 4; mt++)
#pragma unroll
        for (int nt = 0; nt < 4; nt++)
#pragma unroll
            for (int j = 0; j < 4; j++) acc[mt][nt][j] = 0.f;

    int KT = K / BKF;

#define LOAD_TILE(kt, st) do { \
    int _k0 = (kt) * BKF; \
    uint32_t _ao = (uint32_t)(st) * ATILE_B; \
    uint32_t _bo = (uint32_t)(st) * BTILE_B; \
    CP_ASYNC16(a_d + _ao,                  asrc + _k0); \
    CP_ASYNC16(a_d + _ao + 64u * 144,      asrc + _k0 + (size_t)64 * K); \
    CP_ASYNC16(b_d + _bo,                  bsrc + (size_t)_k0 * Ntot); \
    CP_ASYNC16(b_d + _bo + 128u,           bsrc + (size_t)_k0 * Ntot + 64); \
    CP_ASYNC16(b_d + _bo + 256u,           bsrc + (size_t)_k0 * Ntot + 128); \
    CP_ASYNC16(b_d + _bo + 384u,           bsrc + (size_t)_k0 * Ntot + 192); \
} while (0)

// Load fragments for k16-step `ks` from smem stage bases into frag buffer `b`.
#define LDFRAG(b, a_s, b_s, ks) do { \
    _Pragma("unroll") \
    for (int _mt = 0; _mt < 4; _mt++) \
        ldsm_x4(afrag[b][_mt], (a_s) + (uint32_t)_mt * 16 * 144 + (uint32_t)(ks) * 32); \
    _Pragma("unroll") \
    for (int _n2 = 0; _n2 < 2; _n2++) { \
        uint32_t _r[4]; \
        ldsm_x4_t(_r, (b_s) + (uint32_t)(ks) * 16 * 528 + (uint32_t)_n2 * 32); \
        bfrag[b][2 * _n2][0] = _r[0]; bfrag[b][2 * _n2][1] = _r[1]; \
        bfrag[b][2 * _n2 + 1][0] = _r[2]; bfrag[b][2 * _n2 + 1][1] = _r[3]; \
    } \
} while (0)

    LOAD_TILE(0, 0); CP_COMMIT();

    uint32_t afrag[2][4][4];
    uint32_t bfrag[2][4][2];

    for (int kt = 0; kt < KT; kt++) {
        int stage = kt & 1;
        CP_WAIT(0);
        __syncthreads();
        if (kt + 1 < KT) {
            LOAD_TILE(kt + 1, stage ^ 1);
            CP_COMMIT();
        }

        uint32_t a_s = a_lm + (uint32_t)stage * ATILE_B;
        uint32_t b_s = b_lm + (uint32_t)stage * BTILE_B;

        LDFRAG(0, a_s, b_s, 0);
#pragma unroll
        for (int ks = 0; ks < 4; ks++) {
            int cur = ks & 1;
            if (ks < 3) LDFRAG(cur ^ 1, a_s, b_s, ks + 1);
#pragma unroll
            for (int mt = 0; mt < 4; mt++)
#pragma unroll
                for (int nt = 0; nt < 4; nt++)
                    mma_f16(acc[mt][nt], afrag[cur][mt], bfrag[cur][nt]);
        }
    }

    // epilogue
#pragma unroll
    for (int mt = 0; mt < 4; mt++) {
        int mrow = row0 + warp_m * 64 + mt * 16 + gid;
#pragma unroll
        for (int nt = 0; nt < 4; nt++) {
            int col = blockIdx.y * BN + warp_n * 32 + nt * 8 + 2 * tig;
            if (doGelu) {
                __half2 h0 = __floats2half2_rn(gelu_tanh(acc[mt][nt][0]),
                                               gelu_tanh(acc[mt][nt][1]));
                __half2 h1 = __floats2half2_rn(gelu_tanh(acc[mt][nt][2]),
                                               gelu_tanh(acc[mt][nt][3]));
                *(__half2*)(g_h + (size_t)mrow * Ntot + col) = h0;
                *(__half2*)(g_h + (size_t)(mrow + 8) * Ntot + col) = h1;
            } else {
                *(float2*)(g_y + (size_t)mrow * Ntot + col) =
                    make_float2(acc[mt][nt][0], acc[mt][nt][1]);
                *(float2*)(g_y + (size_t)(mrow + 8) * Ntot + col) =
                    make_float2(acc[mt][nt][2], acc[mt][nt][3]);
            }
        }
    }
}

__global__ void k_combine(float* __restrict__ out) {
    int t = blockIdx.x * 8 + (threadIdx.x >> 5);
    int lane = threadIdx.x & 31;
    if (t >= T_TOK) return;
    int a0 = g_slot[2 * t], a1 = g_slot[2 * t + 1];
    float w0 = g_tw[2 * t], w1 = g_tw[2 * t + 1];
    const float4* y0 = (const float4*)(g_y + (size_t)a0 * DDIM);
    const float4* y1 = (const float4*)(g_y + (size_t)a1 * DDIM);
    float4* o = (float4*)(out + (size_t)t * DDIM);
#pragma unroll
    for (int i = 0; i < 8; i++) {
        int idx = lane + 32 * i;
        float4 p = y0[idx], q = y1[idx];
        o[idx] = make_float4(w0 * p.x + w1 * q.x, w0 * p.y + w1 * q.y,
                             w0 * p.z + w1 * q.z, w0 * p.w + w1 * q.w);
    }
}

// ---------------------------------------------------------------------------
extern "C" void kernel_launch(void* const* d_in, const int* in_sizes, int n_in,
                              void* d_out, int out_size) {
    const float* x  = (const float*)d_in[0];
    const float* Wg = (const float*)d_in[1];
    const float* w1 = (const float*)d_in[2];
    const float* w2 = (const float*)d_in[3];
    float* out = (float*)d_out;

    cudaFuncSetAttribute(k_gemm_h, cudaFuncAttributeMaxDynamicSharedMemorySize, SMEM_GEMM);

    __half* w1h; cudaGetSymbolAddress((void**)&w1h, g_w1h);
    __half* w2h; cudaGetSymbolAddress((void**)&w2h, g_w2h);
    __half* xph; cudaGetSymbolAddress((void**)&xph, g_xph);
    __half* hbuf; cudaGetSymbolAddress((void**)&hbuf, g_h);

    k_init<<<1, 32>>>();
    k_gate<<<T_TOK / 8, 256>>>(x, Wg);
    k_offs<<<1, 32>>>();

    int n4 = EEXP * DDIM * FDIM / 4;
    k_cvt<<<n4 / 256, 256>>>((const float4*)w1, (uint2*)w1h);
    k_cvt<<<n4 / 256, 256>>>((const float4*)w2, (uint2*)w2h);

    k_gather<<<NASSIGN / 8, 256>>>(x);
    k_zeropad<<<dim3(EEXP, 8), 256>>>();

    dim3 grid1(MAXSLOTS / BM, FDIM / BN);   // (136, 16)
    k_gemm_h<<<grid1, 512, SMEM_GEMM>>>(xph, w1h, DDIM, FDIM, 1);

    dim3 grid2(MAXSLOTS / BM, DDIM / BN);   // (136, 4)
    k_gemm_h<<<grid2, 512, SMEM_GEMM>>>(hbuf, w2h, FDIM, DDIM, 0);

    k_combine<<<T_TOK / 8, 256>>>(out);
}

// round 11
// speedup vs baseline: 3.0107x; 1.0650x over previous
#include <cuda_runtime.h>
#include <cuda_fp16.h>
#include <cstdint>

// ---------------------------------------------------------------------------
// MoE layer: B=4,S=2048,D=1024,E=8,F=4096, top-k=2
// Round 10: 256-thread GEMM CTAs with 2 CTAs/SM (independent barrier domains
// cover each other's ktile-boundary drain). BN=128, warp tile 64x32.
// ---------------------------------------------------------------------------

#define T_TOK   8192
#define DDIM    1024
#define EEXP    8
#define FDIM    4096
#define NASSIGN (T_TOK * 2)
#define SEGPAD  128
#define MAXSLOTS (NASSIGN + EEXP * SEGPAD)  // 17408

__device__ __half g_xph[MAXSLOTS * (size_t)DDIM];
__device__ __half g_h  [MAXSLOTS * (size_t)FDIM];
__device__ float  g_y  [MAXSLOTS * (size_t)DDIM];
__device__ __half g_w1h[(size_t)EEXP * DDIM * FDIM];
__device__ __half g_w2h[(size_t)EEXP * FDIM * DDIM];
__device__ int   g_te[NASSIGN];
__device__ float g_tw[NASSIGN];
__device__ int   g_slot[NASSIGN];
__device__ int   g_count[EEXP];
__device__ int   g_cursor[EEXP];
__device__ int   g_offs[EEXP + 1];

__device__ __forceinline__ uint32_t smem_u32(const void* p) {
    uint32_t a;
    asm("{ .reg .u64 t; cvta.to.shared.u64 t, %1; cvt.u32.u64 %0, t; }" : "=r"(a) : "l"(p));
    return a;
}
#define CP_ASYNC16(dst, src) \
    asm volatile("cp.async.cg.shared.global [%0], [%1], 16;" :: "r"(dst), "l"(src) : "memory")
#define CP_COMMIT() asm volatile("cp.async.commit_group;" ::: "memory")
#define CP_WAIT(n)  asm volatile("cp.async.wait_group %0;" :: "n"(n) : "memory")

__device__ __forceinline__ void mma_f16(float* d, const uint32_t* a, const uint32_t* b) {
    asm volatile(
        "mma.sync.aligned.m16n8k16.row.col.f32.f16.f16.f32 "
        "{%0,%1,%2,%3}, {%4,%5,%6,%7}, {%8,%9}, {%0,%1,%2,%3};"
        : "+f"(d[0]), "+f"(d[1]), "+f"(d[2]), "+f"(d[3])
        : "r"(a[0]), "r"(a[1]), "r"(a[2]), "r"(a[3]), "r"(b[0]), "r"(b[1]));
}
__device__ __forceinline__ void ldsm_x4(uint32_t* r, uint32_t addr) {
    asm volatile("ldmatrix.sync.aligned.m8n8.x4.shared.b16 {%0,%1,%2,%3}, [%4];"
        : "=r"(r[0]), "=r"(r[1]), "=r"(r[2]), "=r"(r[3]) : "r"(addr));
}
__device__ __forceinline__ void ldsm_x4_t(uint32_t* r, uint32_t addr) {
    asm volatile("ldmatrix.sync.aligned.m8n8.x4.trans.shared.b16 {%0,%1,%2,%3}, [%4];"
        : "=r"(r[0]), "=r"(r[1]), "=r"(r[2]), "=r"(r[3]) : "r"(addr));
}

// ---------------------------------------------------------------------------
__global__ void k_init() {
    int i = threadIdx.x;
    if (i < EEXP) { g_count[i] = 0; g_cursor[i] = 0; }
}

// Gate: one warp per token (fp32).
__global__ void k_gate(const float* __restrict__ x, const float* __restrict__ Wg) {
    int t = blockIdx.x * 8 + (threadIdx.x >> 5);
    int lane = threadIdx.x & 31;
    const float* xr = x + (size_t)t * DDIM;

    float acc[EEXP];
#pragma unroll
    for (int e = 0; e < EEXP; e++) acc[e] = 0.f;
#pragma unroll 4
    for (int i = 0; i < DDIM / 32; i++) {
        int d = i * 32 + lane;
        float xv = xr[d];
        const float4* wr = (const float4*)(Wg + (size_t)d * EEXP);
        float4 w0 = wr[0], w1 = wr[1];
        acc[0] += xv * w0.x; acc[1] += xv * w0.y;
        acc[2] += xv * w0.z; acc[3] += xv * w0.w;
        acc[4] += xv * w1.x; acc[5] += xv * w1.y;
        acc[6] += xv * w1.z; acc[7] += xv * w1.w;
    }
#pragma unroll
    for (int off = 16; off > 0; off >>= 1)
#pragma unroll
        for (int e = 0; e < EEXP; e++)
            acc[e] += __shfl_xor_sync(0xffffffffu, acc[e], off);

    if (lane == 0) {
        int i1 = 0;
#pragma unroll
        for (int e = 1; e < EEXP; e++) if (acc[e] > acc[i1]) i1 = e;
        int i2 = -1;
#pragma unroll
        for (int e = 0; e < EEXP; e++) {
            if (e == i1) continue;
            if (i2 < 0 || acc[e] > acc[i2]) i2 = e;
        }
        float wa = 1.f / (1.f + expf(acc[i2] - acc[i1]));
        g_te[2 * t] = i1;  g_te[2 * t + 1] = i2;
        g_tw[2 * t] = wa;  g_tw[2 * t + 1] = 1.f - wa;
        atomicAdd(&g_count[i1], 1);
        atomicAdd(&g_count[i2], 1);
    }
}

__global__ void k_offs() {
    if (threadIdx.x == 0) {
        int o = 0;
#pragma unroll
        for (int e = 0; e < EEXP; e++) {
            g_offs[e] = o;
            o += (g_count[e] + SEGPAD - 1) & ~(SEGPAD - 1);
            g_cursor[e] = 0;
        }
        g_offs[EEXP] = o;
    }
}

// Convert fp32 weights -> fp16 (RN).
__global__ void k_cvt(const float4* __restrict__ src, uint2* __restrict__ dst) {
    int i = blockIdx.x * 256 + threadIdx.x;
    float4 v = src[i];
    __half2 h01 = __floats2half2_rn(v.x, v.y);
    __half2 h23 = __floats2half2_rn(v.z, v.w);
    uint2 u;
    u.x = *(uint32_t*)&h01;
    u.y = *(uint32_t*)&h23;
    dst[i] = u;
}

// Gather: permute + convert x row to fp16.
__global__ void k_gather(const float* __restrict__ x) {
    int a = blockIdx.x * 8 + (threadIdx.x >> 5);
    int lane = threadIdx.x & 31;
    if (a >= NASSIGN) return;
    int t = a >> 1;
    int e = g_te[a];
    int slot = 0;
    if (lane == 0) {
        slot = g_offs[e] + atomicAdd(&g_cursor[e], 1);
        g_slot[a] = slot;
    }
    slot = __shfl_sync(0xffffffffu, slot, 0);
    const float4* src = (const float4*)(x + (size_t)t * DDIM);
    uint2* dst = (uint2*)(g_xph + (size_t)slot * DDIM);
#pragma unroll
    for (int i = 0; i < 8; i++) {
        float4 v = src[lane + 32 * i];
        __half2 h01 = __floats2half2_rn(v.x, v.y);
        __half2 h23 = __floats2half2_rn(v.z, v.w);
        uint2 u;
        u.x = *(uint32_t*)&h01;
        u.y = *(uint32_t*)&h23;
        dst[lane + 32 * i] = u;
    }
}

__global__ void k_zeropad() {
    int e = blockIdx.x;
    int start = g_offs[e] + g_count[e];
    int end = g_offs[e + 1];
    for (int r = start + (int)blockIdx.y; r < end; r += (int)gridDim.y) {
        uint4* dst = (uint4*)(g_xph + (size_t)r * DDIM);
        for (int i = threadIdx.x; i < DDIM * 2 / 16; i += 256)
            dst[i] = make_uint4(0, 0, 0, 0);
    }
}

__device__ __forceinline__ float gelu_tanh(float v) {
    float v3 = v * v * v;
    return 0.5f * v * (1.f + tanhf(0.7978845608028654f * (v + 0.044715f * v3)));
}

// ---------------------------------------------------------------------------
// fp16 mma GEMM, 256 threads, 2 CTAs/SM.
// BM=128, BN=128, BK=64 halves, 8 warps (2 m x 4 n), warp tile 64x32.
// A row stride 144 B, B row stride 272 B (both +16B mod 128: conflict-free).
#define BM 128
#define BN 128
#define BKF 64
#define NSTAGE 2
#define ATILE_B (BM * 72 * 2)        // 18432 B
#define BTILE_B (BKF * 136 * 2)      // 17408 B
#define SMEM_GEMM (NSTAGE * (ATILE_B + BTILE_B))  // 71680 B

__global__ __launch_bounds__(256, 2)
void k_gemm_h(const __half* __restrict__ A, const __half* __restrict__ W,
              int K, int Ntot, int doGelu) {
    int row0 = blockIdx.x * BM;
    if (row0 >= g_offs[EEXP]) return;
    int e = 0;
    while (g_offs[e + 1] <= row0) e++;

    extern __shared__ char smem[];
    uint32_t sbase = smem_u32(smem);

    int tid = threadIdx.x, wid = tid >> 5, lane = tid & 31;
    int gid = lane >> 2, tig = lane & 3;
    int warp_m = wid & 1, warp_n = wid >> 1;   // 2 x 4 warps, warp tile 64x32

    const __half* B = W + (size_t)e * K * Ntot + (size_t)blockIdx.y * BN;

    // A loader: 128 rows x 64 halves = 1024 16B-chunks, 4/thread (rows +32).
    int ar = tid >> 3, ach = tid & 7;
    const __half* asrc = A + (size_t)(row0 + ar) * K + ach * 8;
    uint32_t a_d = sbase + (uint32_t)ar * 144 + (uint32_t)ach * 16;
    // B loader: 64 rows x 128 halves = 1024 chunks, 4/thread (rows +16).
    int br = tid >> 4, bch = tid & 15;
    const __half* bsrc = B + (size_t)br * Ntot + bch * 8;
    uint32_t b_d = sbase + (uint32_t)NSTAGE * ATILE_B + (uint32_t)br * 272 + (uint32_t)bch * 16;

    uint32_t a_lm = sbase + ((uint32_t)(warp_m * 64 + (lane & 15))) * 144 + ((lane >> 4) << 4);
    uint32_t b_row = (lane & 7) + ((lane >> 3) & 1) * 8;
    uint32_t b_ncol = (uint32_t)(warp_n * 32) + ((lane >> 4) << 3);
    uint32_t b_lm = sbase + (uint32_t)NSTAGE * ATILE_B + b_row * 272 + b_ncol * 2;

    float acc[4][4][4];
#pragma unroll
    for (int mt = 0; mt < 4; mt++)
#pragma unroll
        for (int nt = 0; nt < 4; nt++)
#pragma unroll
            for (int j = 0; j < 4; j++) acc[mt][nt][j] = 0.f;

    int KT = K / BKF;

#define LOAD_TILE(kt, st) do { \
    int _k0 = (kt) * BKF; \
    uint32_t _ao = (uint32_t)(st) * ATILE_B; \
    uint32_t _bo = (uint32_t)(st) * BTILE_B; \
    CP_ASYNC16(a_d + _ao,                  asrc + _k0); \
    CP_ASYNC16(a_d + _ao + 32u * 144,      asrc + _k0 + (size_t)32 * K); \
    CP_ASYNC16(a_d + _ao + 64u * 144,      asrc + _k0 + (size_t)64 * K); \
    CP_ASYNC16(a_d + _ao + 96u * 144,      asrc + _k0 + (size_t)96 * K); \
    CP_ASYNC16(b_d + _bo,                  bsrc + (size_t)_k0 * Ntot); \
    CP_ASYNC16(b_d + _bo + 16u * 272,      bsrc + (size_t)(_k0 + 16) * Ntot); \
    CP_ASYNC16(b_d + _bo + 32u * 272,      bsrc + (size_t)(_k0 + 32) * Ntot); \
    CP_ASYNC16(b_d + _bo + 48u * 272,      bsrc + (size_t)(_k0 + 48) * Ntot); \
} while (0)

    LOAD_TILE(0, 0); CP_COMMIT();

    for (int kt = 0; kt < KT; kt++) {
        int stage = kt & 1;
        CP_WAIT(0);
        __syncthreads();
        if (kt + 1 < KT) {
            LOAD_TILE(kt + 1, stage ^ 1);
            CP_COMMIT();
        }

        uint32_t a_s = a_lm + (uint32_t)stage * ATILE_B;
        uint32_t b_s = b_lm + (uint32_t)stage * BTILE_B;
#pragma unroll
        for (int ks = 0; ks < 4; ks++) {
            uint32_t afrag[4][4];
#pragma unroll
            for (int mt = 0; mt < 4; mt++)
                ldsm_x4(afrag[mt], a_s + (uint32_t)mt * 16 * 144 + (uint32_t)ks * 32);
            uint32_t bfrag[4][2];
#pragma unroll
            for (int nt2 = 0; nt2 < 2; nt2++) {
                uint32_t r[4];
                ldsm_x4_t(r, b_s + (uint32_t)ks * 16 * 272 + (uint32_t)nt2 * 32);
                bfrag[2 * nt2][0] = r[0]; bfrag[2 * nt2][1] = r[1];
                bfrag[2 * nt2 + 1][0] = r[2]; bfrag[2 * nt2 + 1][1] = r[3];
            }
#pragma unroll
            for (int mt = 0; mt < 4; mt++)
#pragma unroll
                for (int nt = 0; nt < 4; nt++)
                    mma_f16(acc[mt][nt], afrag[mt], bfrag[nt]);
        }
    }

    // epilogue
#pragma unroll
    for (int mt = 0; mt < 4; mt++) {
        int mrow = row0 + warp_m * 64 + mt * 16 + gid;
#pragma unroll
        for (int nt = 0; nt < 4; nt++) {
            int col = blockIdx.y * BN + warp_n * 32 + nt * 8 + 2 * tig;
            if (doGelu) {
                __half2 h0 = __floats2half2_rn(gelu_tanh(acc[mt][nt][0]),
                                               gelu_tanh(acc[mt][nt][1]));
                __half2 h1 = __floats2half2_rn(gelu_tanh(acc[mt][nt][2]),
                                               gelu_tanh(acc[mt][nt][3]));
                *(__half2*)(g_h + (size_t)mrow * Ntot + col) = h0;
                *(__half2*)(g_h + (size_t)(mrow + 8) * Ntot + col) = h1;
            } else {
                *(float2*)(g_y + (size_t)mrow * Ntot + col) =
                    make_float2(acc[mt][nt][0], acc[mt][nt][1]);
                *(float2*)(g_y + (size_t)(mrow + 8) * Ntot + col) =
                    make_float2(acc[mt][nt][2], acc[mt][nt][3]);
            }
        }
    }
}

__global__ void k_combine(float* __restrict__ out) {
    int t = blockIdx.x * 8 + (threadIdx.x >> 5);
    int lane = threadIdx.x & 31;
    if (t >= T_TOK) return;
    int a0 = g_slot[2 * t], a1 = g_slot[2 * t + 1];
    float w0 = g_tw[2 * t], w1 = g_tw[2 * t + 1];
    const float4* y0 = (const float4*)(g_y + (size_t)a0 * DDIM);
    const float4* y1 = (const float4*)(g_y + (size_t)a1 * DDIM);
    float4* o = (float4*)(out + (size_t)t * DDIM);
#pragma unroll
    for (int i = 0; i < 8; i++) {
        int idx = lane + 32 * i;
        float4 p = y0[idx], q = y1[idx];
        o[idx] = make_float4(w0 * p.x + w1 * q.x, w0 * p.y + w1 * q.y,
                             w0 * p.z + w1 * q.z, w0 * p.w + w1 * q.w);
    }
}

// ---------------------------------------------------------------------------
extern "C" void kernel_launch(void* const* d_in, const int* in_sizes, int n_in,
                              void* d_out, int out_size) {
    const float* x  = (const float*)d_in[0];
    const float* Wg = (const float*)d_in[1];
    const float* w1 = (const float*)d_in[2];
    const float* w2 = (const float*)d_in[3];
    float* out = (float*)d_out;

    cudaFuncSetAttribute(k_gemm_h, cudaFuncAttributeMaxDynamicSharedMemorySize, SMEM_GEMM);

    __half* w1h; cudaGetSymbolAddress((void**)&w1h, g_w1h);
    __half* w2h; cudaGetSymbolAddress((void**)&w2h, g_w2h);
    __half* xph; cudaGetSymbolAddress((void**)&xph, g_xph);
    __half* hbuf; cudaGetSymbolAddress((void**)&hbuf, g_h);

    k_init<<<1, 32>>>();
    k_gate<<<T_TOK / 8, 256>>>(x, Wg);
    k_offs<<<1, 32>>>();

    int n4 = EEXP * DDIM * FDIM / 4;
    k_cvt<<<n4 / 256, 256>>>((const float4*)w1, (uint2*)w1h);
    k_cvt<<<n4 / 256, 256>>>((const float4*)w2, (uint2*)w2h);

    k_gather<<<NASSIGN / 8, 256>>>(x);
    k_zeropad<<<dim3(EEXP, 8), 256>>>();

    dim3 grid1(MAXSLOTS / BM, FDIM / BN);   // (136, 32)
    k_gemm_h<<<grid1, 256, SMEM_GEMM>>>(xph, w1h, DDIM, FDIM, 1);

    dim3 grid2(MAXSLOTS / BM, DDIM / BN);   // (136, 8)
    k_gemm_h<<<grid2, 256, SMEM_GEMM>>>(hbuf, w2h, FDIM, DDIM, 0);

    k_combine<<<T_TOK / 8, 256>>>(out);
}